// round 5
// baseline (speedup 1.0000x reference)
#include <cuda_runtime.h>
#include <cuda_bf16.h>
#include <cstdint>
#include <math.h>

#define BB 2
#define HH 16
#define SQ 2048
#define DDIM 64
#define MQ 128
#define TKEY 128
#define NTILE (SQ / TKEY)
#define NTH 256
#define NEGB (-1.0e9f)

// smem layout (u32 units)
#define U_KH 0
#define U_KL 8192
#define U_VH 16384
#define U_VL 24576
#define U_BIAS 32768          // [2][128] float
#define U_LSUM 33024          // [128] float
#define U_INV  33152          // [128] float
#define SMEM_BYTES (33280 * 4)

static __device__ __forceinline__ void mma_bf16(float* c, const uint32_t* a, const uint32_t* b) {
    asm volatile(
        "mma.sync.aligned.m16n8k16.row.col.f32.bf16.bf16.f32 "
        "{%0,%1,%2,%3}, {%4,%5,%6,%7}, {%8,%9}, {%0,%1,%2,%3};"
        : "+f"(c[0]), "+f"(c[1]), "+f"(c[2]), "+f"(c[3])
        : "r"(a[0]), "r"(a[1]), "r"(a[2]), "r"(a[3]), "r"(b[0]), "r"(b[1]));
}

static __device__ __forceinline__ void split2(float a, float b, uint32_t& hi, uint32_t& lo) {
    __nv_bfloat162 h = __floats2bfloat162_rn(a, b);
    float ra = a - __bfloat162float(__low2bfloat16(h));
    float rb = b - __bfloat162float(__high2bfloat16(h));
    __nv_bfloat162 l = __floats2bfloat162_rn(ra, rb);
    hi = *reinterpret_cast<uint32_t*>(&h);
    lo = *reinterpret_cast<uint32_t*>(&l);
}

__global__ __launch_bounds__(NTH, 1)
void attn5(const float* __restrict__ Q, const float* __restrict__ K,
           const float* __restrict__ V, const int* __restrict__ M,
           float* __restrict__ Out, float* __restrict__ W) {
    extern __shared__ __align__(16) uint32_t smu[];
    float* smf = (float*)smu;

    const int t    = threadIdx.x;
    const int lane = t & 31;
    const int g    = lane >> 2;
    const int t4   = lane & 3;
    const int dlo  = 2 * t4;
    const int qb   = (t >> 5) * 16;

    const int qt = blockIdx.x;
    const int bh = blockIdx.y;
    const int b  = bh / HH;

    const float* qg = Q + ((size_t)bh * SQ + (size_t)qt * MQ) * DDIM;
    const float* kg = K + (size_t)bh * SQ * DDIM;
    const float* vg = V + (size_t)bh * SQ * DDIM;
    const int*   mg = M + b * SQ;

    // ---- producers: split once per element into frag-native hi/lo slots ----
    auto prodK = [&](int buf, int kt) {
        const float2* src = (const float2*)(kg + (size_t)kt * TKEY * DDIM);
        uint32_t* KHb = smu + U_KH + buf * 4096;
        uint32_t* KLb = smu + U_KL + buf * 4096;
        #pragma unroll
        for (int grp = 0; grp < 2; grp++) {
            float2 x[8];
            #pragma unroll
            for (int i = 0; i < 8; i++) x[i] = src[(grp * 8 + i) * NTH + t];
            #pragma unroll
            for (int i = 0; i < 8; i++) {
                int idx = (grp * 8 + i) * NTH + t;
                int key = idx >> 5, dp = idx & 31;
                int slot = (key >> 3) * 256 + (dp >> 3) * 64
                         + ((key & 7) * 4 + (dp & 3)) * 2 + ((dp >> 2) & 1);
                uint32_t hi, lo; split2(x[i].x, x[i].y, hi, lo);
                KHb[slot] = hi; KLb[slot] = lo;
            }
        }
    };
    auto prodV = [&](int buf, int kt) {
        const float* src = vg + (size_t)kt * TKEY * DDIM;
        uint32_t* VHb = smu + U_VH + buf * 4096;
        uint32_t* VLb = smu + U_VL + buf * 4096;
        #pragma unroll
        for (int grp = 0; grp < 2; grp++) {
            float va[8], vb[8];
            #pragma unroll
            for (int i = 0; i < 8; i++) {
                int idx = (grp * 8 + i) * NTH + t;
                int d = idx & 63, kp = idx >> 6;
                va[i] = src[(size_t)(2 * kp) * DDIM + d];
                vb[i] = src[(size_t)(2 * kp + 1) * DDIM + d];
            }
            #pragma unroll
            for (int i = 0; i < 8; i++) {
                int idx = (grp * 8 + i) * NTH + t;
                int d = idx & 63, kp = idx >> 6;
                int kc2 = kp >> 3, w8 = kp & 7;
                int slot = kc2 * 512 + (d >> 3) * 64
                         + ((d & 7) * 4 + (w8 & 3)) * 2 + (w8 >> 2);
                uint32_t hi, lo; split2(va[i], vb[i], hi, lo);
                VHb[slot] = hi; VLb[slot] = lo;
            }
        }
    };
    auto prodB = [&](int buf, int kt) {
        if (t < TKEY) smf[U_BIAS + buf * 128 + t] = mg[kt * TKEY + t] ? 0.f : NEGB;
    };

    // ---- persistent Q A-fragments (hi/lo) ----
    uint32_t AH[4][4], AL[4][4];
    #pragma unroll
    for (int kc = 0; kc < 4; kc++) {
        const float* r0 = qg + (size_t)(qb + g) * DDIM + kc * 16 + dlo;
        const float* r1 = r0 + 8 * DDIM;
        float2 p0 = *(const float2*)(r0);
        float2 p1 = *(const float2*)(r1);
        float2 p2 = *(const float2*)(r0 + 8);
        float2 p3 = *(const float2*)(r1 + 8);
        split2(p0.x, p0.y, AH[kc][0], AL[kc][0]);
        split2(p1.x, p1.y, AH[kc][1], AL[kc][1]);
        split2(p2.x, p2.y, AH[kc][2], AL[kc][2]);
        split2(p3.x, p3.y, AH[kc][3], AL[kc][3]);
    }

    // QK chunk kernels: c[nt][term][4]
    auto qk2 = [&](const uint32_t* KHb, const uint32_t* KLb, int kc2, float (&c)[2][2][4]) {
        #pragma unroll
        for (int nt = 0; nt < 2; nt++)
            #pragma unroll
            for (int s = 0; s < 2; s++)
                c[nt][s][0] = c[nt][s][1] = c[nt][s][2] = c[nt][s][3] = 0.f;
        #pragma unroll
        for (int kcd = 0; kcd < 4; kcd++) {
            #pragma unroll
            for (int nt = 0; nt < 2; nt++) {
                int base = (kc2 * 2 + nt) * 256 + kcd * 64 + lane * 2;
                uint32_t bh2[2], bl2[2];
                *(uint2*)bh2 = *(const uint2*)&KHb[base];
                *(uint2*)bl2 = *(const uint2*)&KLb[base];
                mma_bf16(c[nt][0], AH[kcd], bh2);
                mma_bf16(c[nt][1], AH[kcd], bl2);
            }
        }
    };
    auto qk3 = [&](const uint32_t* KHb, const uint32_t* KLb, int kc2, float (&c)[2][2][4]) {
        #pragma unroll
        for (int nt = 0; nt < 2; nt++)
            #pragma unroll
            for (int s = 0; s < 2; s++)
                c[nt][s][0] = c[nt][s][1] = c[nt][s][2] = c[nt][s][3] = 0.f;
        #pragma unroll
        for (int kcd = 0; kcd < 4; kcd++) {
            #pragma unroll
            for (int nt = 0; nt < 2; nt++) {
                int base = (kc2 * 2 + nt) * 256 + kcd * 64 + lane * 2;
                uint32_t bh2[2], bl2[2];
                *(uint2*)bh2 = *(const uint2*)&KHb[base];
                *(uint2*)bl2 = *(const uint2*)&KLb[base];
                mma_bf16(c[nt][0], AH[kcd], bh2);
                mma_bf16(c[nt][1], AH[kcd], bl2);
                mma_bf16(c[nt][1], AL[kcd], bh2);
            }
        }
    };

    // ================= PASS 1: row sums (2-term QK) =================
    prodK(0, 0); prodB(0, 0);
    __syncthreads();

    float rs0 = 0.f, rs1 = 0.f;
    for (int kt = 0; kt < NTILE; kt++) {
        const int cur = kt & 1;
        if (kt < NTILE - 1) { prodK(cur ^ 1, kt + 1); prodB(cur ^ 1, kt + 1); }
        const uint32_t* KHb = smu + U_KH + cur * 4096;
        const uint32_t* KLb = smu + U_KL + cur * 4096;
        const float* bb = smf + U_BIAS + cur * 128;

        float c[2][2][2][4];
        qk2(KHb, KLb, 0, c[0]);
        #pragma unroll
        for (int kc2 = 0; kc2 < 8; kc2++) {
            if (kc2 < 7) qk2(KHb, KLb, kc2 + 1, c[(kc2 + 1) & 1]);
            float (&cc)[2][2][4] = c[kc2 & 1];
            int key0 = kc2 * 16 + dlo;
            float b0 = bb[key0], b1 = bb[key0 + 1], b2 = bb[key0 + 8], b3 = bb[key0 + 9];
            rs0 += __expf(fmaf(cc[0][0][0] + cc[0][1][0], 0.125f, b0))
                 + __expf(fmaf(cc[0][0][1] + cc[0][1][1], 0.125f, b1))
                 + __expf(fmaf(cc[1][0][0] + cc[1][1][0], 0.125f, b2))
                 + __expf(fmaf(cc[1][0][1] + cc[1][1][1], 0.125f, b3));
            rs1 += __expf(fmaf(cc[0][0][2] + cc[0][1][2], 0.125f, b0))
                 + __expf(fmaf(cc[0][0][3] + cc[0][1][3], 0.125f, b1))
                 + __expf(fmaf(cc[1][0][2] + cc[1][1][2], 0.125f, b2))
                 + __expf(fmaf(cc[1][0][3] + cc[1][1][3], 0.125f, b3));
        }
        __syncthreads();
    }
    rs0 += __shfl_xor_sync(0xffffffffu, rs0, 1);
    rs0 += __shfl_xor_sync(0xffffffffu, rs0, 2);
    rs1 += __shfl_xor_sync(0xffffffffu, rs1, 1);
    rs1 += __shfl_xor_sync(0xffffffffu, rs1, 2);
    if (t4 == 0) {
        smf[U_LSUM + qb + g] = rs0;
        smf[U_LSUM + qb + g + 8] = rs1;
    }
    __syncthreads();
    if (t < MQ) smf[U_INV + t] = 1.f / smf[U_LSUM + t];
    prodK(0, 0); prodV(0, 0); prodB(0, 0);
    __syncthreads();

    const float inv0 = smf[U_INV + qb + g];
    const float inv1 = smf[U_INV + qb + g + 8];

    float* wr0 = W + ((size_t)bh * SQ + qt * MQ + qb + g) * SQ;
    float* wr1 = wr0 + (size_t)8 * SQ;

    float accO[8][4];
    #pragma unroll
    for (int j = 0; j < 8; j++)
        accO[j][0] = accO[j][1] = accO[j][2] = accO[j][3] = 0.f;

    // ================= PASS 2: W write + PV =================
    for (int kt = 0; kt < NTILE; kt++) {
        const int cur = kt & 1;
        if (kt < NTILE - 1) {
            prodK(cur ^ 1, kt + 1); prodV(cur ^ 1, kt + 1); prodB(cur ^ 1, kt + 1);
        }
        const uint32_t* KHb = smu + U_KH + cur * 4096;
        const uint32_t* KLb = smu + U_KL + cur * 4096;
        const uint32_t* VHb = smu + U_VH + cur * 4096;
        const uint32_t* VLb = smu + U_VL + cur * 4096;
        const float* bb = smf + U_BIAS + cur * 128;
        const size_t ktb = (size_t)kt * TKEY;

        float c[2][2][2][4];
        qk3(KHb, KLb, 0, c[0]);
        #pragma unroll
        for (int kc2 = 0; kc2 < 8; kc2++) {
            if (kc2 < 7) qk3(KHb, KLb, kc2 + 1, c[(kc2 + 1) & 1]);
            float (&cP)[2][2][4] = c[kc2 & 1];

            int key0 = kc2 * 16 + dlo;
            float b0 = bb[key0], b1 = bb[key0 + 1], b2 = bb[key0 + 8], b3 = bb[key0 + 9];

            float e00 = __expf(fmaf(cP[0][0][0] + cP[0][1][0], 0.125f, b0)) * inv0;
            float e01 = __expf(fmaf(cP[0][0][1] + cP[0][1][1], 0.125f, b1)) * inv0;
            float e02 = __expf(fmaf(cP[0][0][2] + cP[0][1][2], 0.125f, b0)) * inv1;
            float e03 = __expf(fmaf(cP[0][0][3] + cP[0][1][3], 0.125f, b1)) * inv1;
            float e10 = __expf(fmaf(cP[1][0][0] + cP[1][1][0], 0.125f, b2)) * inv0;
            float e11 = __expf(fmaf(cP[1][0][1] + cP[1][1][1], 0.125f, b3)) * inv0;
            float e12 = __expf(fmaf(cP[1][0][2] + cP[1][1][2], 0.125f, b2)) * inv1;
            float e13 = __expf(fmaf(cP[1][0][3] + cP[1][1][3], 0.125f, b3)) * inv1;

            size_t cb = ktb + key0;
            *(float2*)(wr0 + cb)     = make_float2(e00, e01);
            *(float2*)(wr1 + cb)     = make_float2(e02, e03);
            *(float2*)(wr0 + cb + 8) = make_float2(e10, e11);
            *(float2*)(wr1 + cb + 8) = make_float2(e12, e13);

            uint32_t aWH[4], aWL[4];
            split2(e00, e01, aWH[0], aWL[0]);
            split2(e02, e03, aWH[1], aWL[1]);
            split2(e10, e11, aWH[2], aWL[2]);
            split2(e12, e13, aWH[3], aWL[3]);

            uint32_t bhh[8][2], bll[8][2];
            #pragma unroll
            for (int ntd = 0; ntd < 8; ntd++) {
                int base = kc2 * 512 + ntd * 64 + lane * 2;
                *(uint2*)bhh[ntd] = *(const uint2*)&VHb[base];
                *(uint2*)bll[ntd] = *(const uint2*)&VLb[base];
            }
            #pragma unroll
            for (int ntd = 0; ntd < 8; ntd++) mma_bf16(accO[ntd], aWH, bhh[ntd]);
            #pragma unroll
            for (int ntd = 0; ntd < 8; ntd++) mma_bf16(accO[ntd], aWL, bhh[ntd]);
            #pragma unroll
            for (int ntd = 0; ntd < 8; ntd++) mma_bf16(accO[ntd], aWH, bll[ntd]);
        }
        __syncthreads();
    }

    // ---- output ----
    float* or0 = Out + ((size_t)bh * SQ + qt * MQ + qb + g) * DDIM + dlo;
    float* or1 = or0 + (size_t)8 * DDIM;
    #pragma unroll
    for (int ntd = 0; ntd < 8; ntd++) {
        *(float2*)(or0 + ntd * 8) = make_float2(accO[ntd][0], accO[ntd][1]);
        *(float2*)(or1 + ntd * 8) = make_float2(accO[ntd][2], accO[ntd][3]);
    }
}

extern "C" void kernel_launch(void* const* d_in, const int* in_sizes, int n_in,
                              void* d_out, int out_size) {
    const float* q = (const float*)d_in[0];
    const float* k = (const float*)d_in[1];
    const float* v = (const float*)d_in[2];
    const int*   m = (const int*)d_in[3];

    float* out = (float*)d_out;
    float* wts = out + (size_t)BB * HH * SQ * DDIM;

    cudaFuncSetAttribute(attn5, cudaFuncAttributeMaxDynamicSharedMemorySize, SMEM_BYTES);
    dim3 grid(SQ / MQ, BB * HH);
    attn5<<<grid, NTH, SMEM_BYTES>>>(q, k, v, m, out, wts);
}

// round 6
// speedup vs baseline: 1.0633x; 1.0633x over previous
#include <cuda_runtime.h>
#include <cuda_bf16.h>
#include <cstdint>
#include <math.h>

#define BB 2
#define HH 16
#define SQ 2048
#define DDIM 64
#define MQ 128
#define TKEY 128
#define NTILE (SQ / TKEY)
#define NTH 256
#define NEGB (-1.0e9f)

// smem layout (u32 units)
#define U_KH 0
#define U_KL 8192
#define U_VH 16384
#define U_VL 24576
#define U_BIAS 32768          // [2][128] float
#define U_LSUM 33024          // [128] float
#define U_INV  33152          // [128] float
#define SMEM_BYTES (33280 * 4)

static __device__ __forceinline__ void mma_bf16(float* c, const uint32_t* a, const uint32_t* b) {
    asm volatile(
        "mma.sync.aligned.m16n8k16.row.col.f32.bf16.bf16.f32 "
        "{%0,%1,%2,%3}, {%4,%5,%6,%7}, {%8,%9}, {%0,%1,%2,%3};"
        : "+f"(c[0]), "+f"(c[1]), "+f"(c[2]), "+f"(c[3])
        : "r"(a[0]), "r"(a[1]), "r"(a[2]), "r"(a[3]), "r"(b[0]), "r"(b[1]));
}

static __device__ __forceinline__ void split2(float a, float b, uint32_t& hi, uint32_t& lo) {
    __nv_bfloat162 h = __floats2bfloat162_rn(a, b);
    float ra = a - __bfloat162float(__low2bfloat16(h));
    float rb = b - __bfloat162float(__high2bfloat16(h));
    __nv_bfloat162 l = __floats2bfloat162_rn(ra, rb);
    hi = *reinterpret_cast<uint32_t*>(&h);
    lo = *reinterpret_cast<uint32_t*>(&l);
}

__global__ __launch_bounds__(NTH, 1)
void attn6(const float* __restrict__ Q, const float* __restrict__ K,
           const float* __restrict__ V, const int* __restrict__ M,
           float* __restrict__ Out, float* __restrict__ W) {
    extern __shared__ __align__(16) uint32_t smu[];
    float* smf = (float*)smu;

    const int t    = threadIdx.x;
    const int lane = t & 31;
    const int g    = lane >> 2;
    const int t4   = lane & 3;
    const int dlo  = 2 * t4;
    const int qb   = (t >> 5) * 16;

    const int qt = blockIdx.x;
    const int bh = blockIdx.y;
    const int b  = bh / HH;

    const float* qg = Q + ((size_t)bh * SQ + (size_t)qt * MQ) * DDIM;
    const float* kg = K + (size_t)bh * SQ * DDIM;
    const float* vg = V + (size_t)bh * SQ * DDIM;
    const int*   mg = M + b * SQ;

    // ---- staged producers: LDG phase (regs) / STS phase (split + frag slots) ----
    auto ldgK = [&](int kt, float2 (&xk)[16]) {
        const float2* src = (const float2*)(kg + (size_t)kt * TKEY * DDIM);
        #pragma unroll
        for (int i = 0; i < 16; i++) xk[i] = src[i * NTH + t];
    };
    auto stsK = [&](int buf, const float2 (&xk)[16]) {
        uint32_t* KHb = smu + U_KH + buf * 4096;
        uint32_t* KLb = smu + U_KL + buf * 4096;
        #pragma unroll
        for (int i = 0; i < 16; i++) {
            int idx = i * NTH + t;
            int key = idx >> 5, dp = idx & 31;
            int slot = (key >> 3) * 256 + (dp >> 3) * 64
                     + ((key & 7) * 4 + (dp & 3)) * 2 + ((dp >> 2) & 1);
            uint32_t hi, lo; split2(xk[i].x, xk[i].y, hi, lo);
            KHb[slot] = hi; KLb[slot] = lo;
        }
    };
    auto ldgV = [&](int kt, float (&va)[16], float (&vb)[16]) {
        const float* src = vg + (size_t)kt * TKEY * DDIM;
        #pragma unroll
        for (int i = 0; i < 16; i++) {
            int idx = i * NTH + t;
            int d = idx & 63, kp = idx >> 6;
            va[i] = src[(size_t)(2 * kp) * DDIM + d];
            vb[i] = src[(size_t)(2 * kp + 1) * DDIM + d];
        }
    };
    auto stsV = [&](int buf, const float (&va)[16], const float (&vb)[16]) {
        uint32_t* VHb = smu + U_VH + buf * 4096;
        uint32_t* VLb = smu + U_VL + buf * 4096;
        #pragma unroll
        for (int i = 0; i < 16; i++) {
            int idx = i * NTH + t;
            int d = idx & 63, kp = idx >> 6;
            int kc2 = kp >> 3, w8 = kp & 7;
            int slot = kc2 * 512 + (d >> 3) * 64
                     + ((d & 7) * 4 + (w8 & 3)) * 2 + (w8 >> 2);
            uint32_t hi, lo; split2(va[i], vb[i], hi, lo);
            VHb[slot] = hi; VLb[slot] = lo;
        }
    };
    auto ldgB = [&](int kt) -> float {
        if (t < TKEY) return mg[kt * TKEY + t] ? 0.f : NEGB;
        return 0.f;
    };
    auto stsB = [&](int buf, float bv) {
        if (t < TKEY) smf[U_BIAS + buf * 128 + t] = bv;
    };

    // ---- persistent Q A-fragments (hi/lo) ----
    uint32_t AH[4][4], AL[4][4];
    #pragma unroll
    for (int kc = 0; kc < 4; kc++) {
        const float* r0 = qg + (size_t)(qb + g) * DDIM + kc * 16 + dlo;
        const float* r1 = r0 + 8 * DDIM;
        float2 p0 = *(const float2*)(r0);
        float2 p1 = *(const float2*)(r1);
        float2 p2 = *(const float2*)(r0 + 8);
        float2 p3 = *(const float2*)(r1 + 8);
        split2(p0.x, p0.y, AH[kc][0], AL[kc][0]);
        split2(p1.x, p1.y, AH[kc][1], AL[kc][1]);
        split2(p2.x, p2.y, AH[kc][2], AL[kc][2]);
        split2(p3.x, p3.y, AH[kc][3], AL[kc][3]);
    }

    // QK chunk kernels: c[nt][chain][4]
    auto qk2 = [&](const uint32_t* KHb, const uint32_t* KLb, int kc2, float (&c)[2][2][4]) {
        #pragma unroll
        for (int nt = 0; nt < 2; nt++)
            #pragma unroll
            for (int s = 0; s < 2; s++)
                c[nt][s][0] = c[nt][s][1] = c[nt][s][2] = c[nt][s][3] = 0.f;
        #pragma unroll
        for (int kcd = 0; kcd < 4; kcd++) {
            #pragma unroll
            for (int nt = 0; nt < 2; nt++) {
                int base = (kc2 * 2 + nt) * 256 + kcd * 64 + lane * 2;
                uint32_t bh2[2], bl2[2];
                *(uint2*)bh2 = *(const uint2*)&KHb[base];
                *(uint2*)bl2 = *(const uint2*)&KLb[base];
                mma_bf16(c[nt][0], AH[kcd], bh2);
                mma_bf16(c[nt][1], AH[kcd], bl2);
            }
        }
    };
    auto qk3 = [&](const uint32_t* KHb, const uint32_t* KLb, int kc2, float (&c)[2][2][4]) {
        #pragma unroll
        for (int nt = 0; nt < 2; nt++)
            #pragma unroll
            for (int s = 0; s < 2; s++)
                c[nt][s][0] = c[nt][s][1] = c[nt][s][2] = c[nt][s][3] = 0.f;
        #pragma unroll
        for (int kcd = 0; kcd < 4; kcd++) {
            #pragma unroll
            for (int nt = 0; nt < 2; nt++) {
                int base = (kc2 * 2 + nt) * 256 + kcd * 64 + lane * 2;
                uint32_t bh2[2], bl2[2];
                *(uint2*)bh2 = *(const uint2*)&KHb[base];
                *(uint2*)bl2 = *(const uint2*)&KLb[base];
                mma_bf16(c[nt][0], AH[kcd], bh2);
                mma_bf16(c[nt][1], AH[kcd], bl2);
                mma_bf16(c[nt][1], AL[kcd], bh2);
            }
        }
    };

    // ================= PASS 1: row sums (2-term QK) =================
    {
        float2 xk[16]; ldgK(0, xk);
        float bv = ldgB(0);
        stsK(0, xk); stsB(0, bv);
    }
    __syncthreads();

    float rs0 = 0.f, rs1 = 0.f;
    for (int kt = 0; kt < NTILE; kt++) {
        const int cur = kt & 1;
        const bool pf = (kt < NTILE - 1);
        float2 xk[16]; float bv = 0.f;
        if (pf) { ldgK(kt + 1, xk); bv = ldgB(kt + 1); }

        const uint32_t* KHb = smu + U_KH + cur * 4096;
        const uint32_t* KLb = smu + U_KL + cur * 4096;
        const float* bb = smf + U_BIAS + cur * 128;

        float c[2][2][2][4];
        qk2(KHb, KLb, 0, c[0]);
        #pragma unroll
        for (int kc2 = 0; kc2 < 8; kc2++) {
            if (kc2 < 7) qk2(KHb, KLb, kc2 + 1, c[(kc2 + 1) & 1]);
            float (&cc)[2][2][4] = c[kc2 & 1];
            int key0 = kc2 * 16 + dlo;
            float b0 = bb[key0], b1 = bb[key0 + 1], b2 = bb[key0 + 8], b3 = bb[key0 + 9];
            rs0 += __expf(fmaf(cc[0][0][0] + cc[0][1][0], 0.125f, b0))
                 + __expf(fmaf(cc[0][0][1] + cc[0][1][1], 0.125f, b1))
                 + __expf(fmaf(cc[1][0][0] + cc[1][1][0], 0.125f, b2))
                 + __expf(fmaf(cc[1][0][1] + cc[1][1][1], 0.125f, b3));
            rs1 += __expf(fmaf(cc[0][0][2] + cc[0][1][2], 0.125f, b0))
                 + __expf(fmaf(cc[0][0][3] + cc[0][1][3], 0.125f, b1))
                 + __expf(fmaf(cc[1][0][2] + cc[1][1][2], 0.125f, b2))
                 + __expf(fmaf(cc[1][0][3] + cc[1][1][3], 0.125f, b3));
            if (kc2 == 2 && pf) { stsK(cur ^ 1, xk); stsB(cur ^ 1, bv); }
        }
        __syncthreads();
    }
    rs0 += __shfl_xor_sync(0xffffffffu, rs0, 1);
    rs0 += __shfl_xor_sync(0xffffffffu, rs0, 2);
    rs1 += __shfl_xor_sync(0xffffffffu, rs1, 1);
    rs1 += __shfl_xor_sync(0xffffffffu, rs1, 2);
    if (t4 == 0) {
        smf[U_LSUM + qb + g] = rs0;
        smf[U_LSUM + qb + g + 8] = rs1;
    }
    __syncthreads();
    if (t < MQ) smf[U_INV + t] = 1.f / smf[U_LSUM + t];
    {
        float2 xk[16]; ldgK(0, xk);
        float va[16], vb[16]; ldgV(0, va, vb);
        float bv = ldgB(0);
        stsK(0, xk); stsV(0, va, vb); stsB(0, bv);
    }
    __syncthreads();

    const float inv0 = smf[U_INV + qb + g];
    const float inv1 = smf[U_INV + qb + g + 8];

    float* wr0 = W + ((size_t)bh * SQ + qt * MQ + qb + g) * SQ;
    float* wr1 = wr0 + (size_t)8 * SQ;

    float accO[8][4];
    #pragma unroll
    for (int j = 0; j < 8; j++)
        accO[j][0] = accO[j][1] = accO[j][2] = accO[j][3] = 0.f;

    // ================= PASS 2: W write + PV =================
    for (int kt = 0; kt < NTILE; kt++) {
        const int cur = kt & 1;
        const bool pf = (kt < NTILE - 1);
        float2 xk[16]; float va[16], vb[16]; float bv = 0.f;
        if (pf) { ldgK(kt + 1, xk); ldgV(kt + 1, va, vb); bv = ldgB(kt + 1); }

        const uint32_t* KHb = smu + U_KH + cur * 4096;
        const uint32_t* KLb = smu + U_KL + cur * 4096;
        const uint32_t* VHb = smu + U_VH + cur * 4096;
        const uint32_t* VLb = smu + U_VL + cur * 4096;
        const float* bb = smf + U_BIAS + cur * 128;
        const size_t ktb = (size_t)kt * TKEY;

        float c[2][2][2][4];
        qk3(KHb, KLb, 0, c[0]);
        #pragma unroll
        for (int kc2 = 0; kc2 < 8; kc2++) {
            if (kc2 < 7) qk3(KHb, KLb, kc2 + 1, c[(kc2 + 1) & 1]);
            float (&cP)[2][2][4] = c[kc2 & 1];

            int key0 = kc2 * 16 + dlo;
            float b0 = bb[key0], b1 = bb[key0 + 1], b2 = bb[key0 + 8], b3 = bb[key0 + 9];

            float e00 = __expf(fmaf(cP[0][0][0] + cP[0][1][0], 0.125f, b0)) * inv0;
            float e01 = __expf(fmaf(cP[0][0][1] + cP[0][1][1], 0.125f, b1)) * inv0;
            float e02 = __expf(fmaf(cP[0][0][2] + cP[0][1][2], 0.125f, b0)) * inv1;
            float e03 = __expf(fmaf(cP[0][0][3] + cP[0][1][3], 0.125f, b1)) * inv1;
            float e10 = __expf(fmaf(cP[1][0][0] + cP[1][1][0], 0.125f, b2)) * inv0;
            float e11 = __expf(fmaf(cP[1][0][1] + cP[1][1][1], 0.125f, b3)) * inv0;
            float e12 = __expf(fmaf(cP[1][0][2] + cP[1][1][2], 0.125f, b2)) * inv1;
            float e13 = __expf(fmaf(cP[1][0][3] + cP[1][1][3], 0.125f, b3)) * inv1;

            size_t cb = ktb + key0;
            *(float2*)(wr0 + cb)     = make_float2(e00, e01);
            *(float2*)(wr1 + cb)     = make_float2(e02, e03);
            *(float2*)(wr0 + cb + 8) = make_float2(e10, e11);
            *(float2*)(wr1 + cb + 8) = make_float2(e12, e13);

            uint32_t aWH[4], aWL[4];
            split2(e00, e01, aWH[0], aWL[0]);
            split2(e02, e03, aWH[1], aWL[1]);
            split2(e10, e11, aWH[2], aWL[2]);
            split2(e12, e13, aWH[3], aWL[3]);

            uint32_t bhh[8][2], bll[8][2];
            #pragma unroll
            for (int ntd = 0; ntd < 8; ntd++) {
                int base = kc2 * 512 + ntd * 64 + lane * 2;
                *(uint2*)bhh[ntd] = *(const uint2*)&VHb[base];
                *(uint2*)bll[ntd] = *(const uint2*)&VLb[base];
            }
            #pragma unroll
            for (int ntd = 0; ntd < 8; ntd++) mma_bf16(accO[ntd], aWH, bhh[ntd]);
            #pragma unroll
            for (int ntd = 0; ntd < 8; ntd++) mma_bf16(accO[ntd], aWL, bhh[ntd]);
            #pragma unroll
            for (int ntd = 0; ntd < 8; ntd++) mma_bf16(accO[ntd], aWH, bll[ntd]);

            if (kc2 == 2 && pf) {
                stsK(cur ^ 1, xk);
                stsV(cur ^ 1, va, vb);
                stsB(cur ^ 1, bv);
            }
        }
        __syncthreads();
    }

    // ---- output ----
    float* or0 = Out + ((size_t)bh * SQ + qt * MQ + qb + g) * DDIM + dlo;
    float* or1 = or0 + (size_t)8 * DDIM;
    #pragma unroll
    for (int ntd = 0; ntd < 8; ntd++) {
        *(float2*)(or0 + ntd * 8) = make_float2(accO[ntd][0], accO[ntd][1]);
        *(float2*)(or1 + ntd * 8) = make_float2(accO[ntd][2], accO[ntd][3]);
    }
}

extern "C" void kernel_launch(void* const* d_in, const int* in_sizes, int n_in,
                              void* d_out, int out_size) {
    const float* q = (const float*)d_in[0];
    const float* k = (const float*)d_in[1];
    const float* v = (const float*)d_in[2];
    const int*   m = (const int*)d_in[3];

    float* out = (float*)d_out;
    float* wts = out + (size_t)BB * HH * SQ * DDIM;

    cudaFuncSetAttribute(attn6, cudaFuncAttributeMaxDynamicSharedMemorySize, SMEM_BYTES);
    dim3 grid(SQ / MQ, BB * HH);
    attn6<<<grid, NTH, SMEM_BYTES>>>(q, k, v, m, out, wts);
}

// round 7
// speedup vs baseline: 1.4043x; 1.3208x over previous
#include <cuda_runtime.h>
#include <cuda_bf16.h>
#include <cstdint>
#include <math.h>

#define BB 2
#define HH 16
#define SQ 2048
#define DDIM 64
#define MQ 128
#define TKEY 128
#define NTILE (SQ / TKEY)
#define NTH 256

// smem layout (u32 units)
#define U_KH 0
#define U_KL 8192
#define U_VH 16384
#define U_VL 24576
#define U_MSK 32768           // [2][128] int
#define U_LSUM 33024          // [128] float
#define U_INV  33152          // [128] float
#define SMEM_BYTES (33280 * 4)

// global scratch: frag-native pre-split K/V (hi/lo bf16x2), 512 tiles x 4096 u32
__device__ uint32_t g_KH[32 * 16 * 4096];
__device__ uint32_t g_KL[32 * 16 * 4096];
__device__ uint32_t g_VH[32 * 16 * 4096];
__device__ uint32_t g_VL[32 * 16 * 4096];

static __device__ __forceinline__ uint32_t smem_u32(const void* p) {
    uint32_t a;
    asm("{ .reg .u64 t; cvta.to.shared.u64 t, %1; cvt.u32.u64 %0, t; }" : "=r"(a) : "l"(p));
    return a;
}
static __device__ __forceinline__ void cp16(uint32_t dst, const void* src) {
    asm volatile("cp.async.cg.shared.global [%0], [%1], 16;" :: "r"(dst), "l"(src));
}
#define CP_COMMIT() asm volatile("cp.async.commit_group;" ::: "memory")
#define CP_WAIT0()  asm volatile("cp.async.wait_group 0;" ::: "memory")
#define CP_WAIT1()  asm volatile("cp.async.wait_group 1;" ::: "memory")

static __device__ __forceinline__ void mma_bf16(float* c, const uint32_t* a, const uint32_t* b) {
    asm volatile(
        "mma.sync.aligned.m16n8k16.row.col.f32.bf16.bf16.f32 "
        "{%0,%1,%2,%3}, {%4,%5,%6,%7}, {%8,%9}, {%0,%1,%2,%3};"
        : "+f"(c[0]), "+f"(c[1]), "+f"(c[2]), "+f"(c[3])
        : "r"(a[0]), "r"(a[1]), "r"(a[2]), "r"(a[3]), "r"(b[0]), "r"(b[1]));
}

static __device__ __forceinline__ void split2(float a, float b, uint32_t& hi, uint32_t& lo) {
    __nv_bfloat162 h = __floats2bfloat162_rn(a, b);
    float ra = a - __bfloat162float(__low2bfloat16(h));
    float rb = b - __bfloat162float(__high2bfloat16(h));
    __nv_bfloat162 l = __floats2bfloat162_rn(ra, rb);
    hi = *reinterpret_cast<uint32_t*>(&h);
    lo = *reinterpret_cast<uint32_t*>(&l);
}

// ---------- prep: split K/V once into frag-native global scratch ----------
__global__ __launch_bounds__(1024)
void prep_split(const float* __restrict__ K, const float* __restrict__ V) {
    const int tile = blockIdx.x;             // bh*16 + kt  (0..511)
    const int t = threadIdx.x;
    const size_t base = (size_t)tile * TKEY * DDIM;
    if (blockIdx.y == 0) {
        const float2* src = (const float2*)(K + base);
        uint32_t* dH = g_KH + (size_t)tile * 4096;
        uint32_t* dL = g_KL + (size_t)tile * 4096;
        #pragma unroll
        for (int i = 0; i < 4; i++) {
            int idx = i * 1024 + t;
            int key = idx >> 5, dp = idx & 31;
            float2 x = src[idx];
            int slot = (key >> 3) * 256 + (dp >> 3) * 64
                     + ((key & 7) * 4 + (dp & 3)) * 2 + ((dp >> 2) & 1);
            uint32_t hi, lo; split2(x.x, x.y, hi, lo);
            dH[slot] = hi; dL[slot] = lo;
        }
    } else {
        const float* src = V + base;
        uint32_t* dH = g_VH + (size_t)tile * 4096;
        uint32_t* dL = g_VL + (size_t)tile * 4096;
        #pragma unroll
        for (int i = 0; i < 4; i++) {
            int idx = i * 1024 + t;
            int d = idx & 63, kp = idx >> 6;
            float va = src[(size_t)(2 * kp) * DDIM + d];
            float vb = src[(size_t)(2 * kp + 1) * DDIM + d];
            int kc2 = kp >> 3, w8 = kp & 7;
            int slot = kc2 * 512 + (d >> 3) * 64
                     + ((d & 7) * 4 + (w8 & 3)) * 2 + (w8 >> 2);
            uint32_t hi, lo; split2(va, vb, hi, lo);
            dH[slot] = hi; dL[slot] = lo;
        }
    }
}

// ---------- main attention kernel ----------
__global__ __launch_bounds__(NTH, 1)
void attn7(const float* __restrict__ Q, const int* __restrict__ M,
           float* __restrict__ Out, float* __restrict__ W) {
    extern __shared__ __align__(16) uint32_t smu[];
    float* smf = (float*)smu;
    const uint32_t sb = smem_u32(smu);

    const int t    = threadIdx.x;
    const int lane = t & 31;
    const int g    = lane >> 2;
    const int t4   = lane & 3;
    const int dlo  = 2 * t4;
    const int qb   = (t >> 5) * 16;

    const int qt = blockIdx.x;
    const int bh = blockIdx.y;
    const int b  = bh / HH;

    const float* qg = Q + ((size_t)bh * SQ + (size_t)qt * MQ) * DDIM;
    const int*   mg = M + b * SQ;

    // cp.async prefetchers (4 x 16B per buffer per thread)
    auto pfK = [&](int buf, int kt) {
        const uint32_t* sH = g_KH + ((size_t)bh * 16 + kt) * 4096;
        const uint32_t* sL = g_KL + ((size_t)bh * 16 + kt) * 4096;
        const uint32_t dH = sb + (U_KH + buf * 4096) * 4;
        const uint32_t dL = sb + (U_KL + buf * 4096) * 4;
        #pragma unroll
        for (int c = 0; c < 4; c++) {
            int o = (c * NTH + t) * 4;
            cp16(dH + o * 4, sH + o);
            cp16(dL + o * 4, sL + o);
        }
    };
    auto pfV = [&](int buf, int kt) {
        const uint32_t* sH = g_VH + ((size_t)bh * 16 + kt) * 4096;
        const uint32_t* sL = g_VL + ((size_t)bh * 16 + kt) * 4096;
        const uint32_t dH = sb + (U_VH + buf * 4096) * 4;
        const uint32_t dL = sb + (U_VL + buf * 4096) * 4;
        #pragma unroll
        for (int c = 0; c < 4; c++) {
            int o = (c * NTH + t) * 4;
            cp16(dH + o * 4, sH + o);
            cp16(dL + o * 4, sL + o);
        }
    };
    auto pfM = [&](int buf, int kt) {
        if (t < 32) cp16(sb + (U_MSK + buf * 128 + t * 4) * 4, mg + kt * TKEY + t * 4);
    };

    // ---- persistent Q A-fragments (hi/lo) ----
    uint32_t AH[4][4], AL[4][4];
    #pragma unroll
    for (int kc = 0; kc < 4; kc++) {
        const float* r0 = qg + (size_t)(qb + g) * DDIM + kc * 16 + dlo;
        const float* r1 = r0 + 8 * DDIM;
        float2 p0 = *(const float2*)(r0);
        float2 p1 = *(const float2*)(r1);
        float2 p2 = *(const float2*)(r0 + 8);
        float2 p3 = *(const float2*)(r1 + 8);
        split2(p0.x, p0.y, AH[kc][0], AL[kc][0]);
        split2(p1.x, p1.y, AH[kc][1], AL[kc][1]);
        split2(p2.x, p2.y, AH[kc][2], AL[kc][2]);
        split2(p3.x, p3.y, AH[kc][3], AL[kc][3]);
    }

    // QK chunk kernels: c[nt][chain][4]
    auto qk2 = [&](const uint32_t* KHb, const uint32_t* KLb, int kc2, float (&c)[2][2][4]) {
        #pragma unroll
        for (int nt = 0; nt < 2; nt++)
            #pragma unroll
            for (int s = 0; s < 2; s++)
                c[nt][s][0] = c[nt][s][1] = c[nt][s][2] = c[nt][s][3] = 0.f;
        #pragma unroll
        for (int kcd = 0; kcd < 4; kcd++) {
            #pragma unroll
            for (int nt = 0; nt < 2; nt++) {
                int base = (kc2 * 2 + nt) * 256 + kcd * 64 + lane * 2;
                uint32_t bh2[2], bl2[2];
                *(uint2*)bh2 = *(const uint2*)&KHb[base];
                *(uint2*)bl2 = *(const uint2*)&KLb[base];
                mma_bf16(c[nt][0], AH[kcd], bh2);
                mma_bf16(c[nt][1], AH[kcd], bl2);
            }
        }
    };
    auto qk3 = [&](const uint32_t* KHb, const uint32_t* KLb, int kc2, float (&c)[2][2][4]) {
        #pragma unroll
        for (int nt = 0; nt < 2; nt++)
            #pragma unroll
            for (int s = 0; s < 2; s++)
                c[nt][s][0] = c[nt][s][1] = c[nt][s][2] = c[nt][s][3] = 0.f;
        #pragma unroll
        for (int kcd = 0; kcd < 4; kcd++) {
            #pragma unroll
            for (int nt = 0; nt < 2; nt++) {
                int base = (kc2 * 2 + nt) * 256 + kcd * 64 + lane * 2;
                uint32_t bh2[2], bl2[2];
                *(uint2*)bh2 = *(const uint2*)&KHb[base];
                *(uint2*)bl2 = *(const uint2*)&KLb[base];
                mma_bf16(c[nt][0], AH[kcd], bh2);
                mma_bf16(c[nt][1], AH[kcd], bl2);
                mma_bf16(c[nt][1], AL[kcd], bh2);
            }
        }
    };

    // ================= PASS 1: row sums (2-term QK) =================
    pfK(0, 0); pfM(0, 0); CP_COMMIT();

    float rs0 = 0.f, rs1 = 0.f;
    for (int kt = 0; kt < NTILE; kt++) {
        const int cur = kt & 1;
        if (kt < NTILE - 1) {
            pfK(cur ^ 1, kt + 1); pfM(cur ^ 1, kt + 1);
            CP_COMMIT(); CP_WAIT1();
        } else {
            CP_WAIT0();
        }
        __syncthreads();

        const uint32_t* KHb = smu + U_KH + cur * 4096;
        const uint32_t* KLb = smu + U_KL + cur * 4096;
        const int* mk = (const int*)(smu + U_MSK + cur * 128);

        float c[2][2][2][4];
        qk2(KHb, KLb, 0, c[0]);
        #pragma unroll
        for (int kc2 = 0; kc2 < 8; kc2++) {
            if (kc2 < 7) qk2(KHb, KLb, kc2 + 1, c[(kc2 + 1) & 1]);
            float (&cc)[2][2][4] = c[kc2 & 1];
            int key0 = kc2 * 16 + dlo;
            int m0 = mk[key0], m1 = mk[key0 + 1], m2 = mk[key0 + 8], m3 = mk[key0 + 9];
            rs0 += (m0 ? __expf((cc[0][0][0] + cc[0][1][0]) * 0.125f) : 0.f)
                 + (m1 ? __expf((cc[0][0][1] + cc[0][1][1]) * 0.125f) : 0.f)
                 + (m2 ? __expf((cc[1][0][0] + cc[1][1][0]) * 0.125f) : 0.f)
                 + (m3 ? __expf((cc[1][0][1] + cc[1][1][1]) * 0.125f) : 0.f);
            rs1 += (m0 ? __expf((cc[0][0][2] + cc[0][1][2]) * 0.125f) : 0.f)
                 + (m1 ? __expf((cc[0][0][3] + cc[0][1][3]) * 0.125f) : 0.f)
                 + (m2 ? __expf((cc[1][0][2] + cc[1][1][2]) * 0.125f) : 0.f)
                 + (m3 ? __expf((cc[1][0][3] + cc[1][1][3]) * 0.125f) : 0.f);
        }
        __syncthreads();
    }
    rs0 += __shfl_xor_sync(0xffffffffu, rs0, 1);
    rs0 += __shfl_xor_sync(0xffffffffu, rs0, 2);
    rs1 += __shfl_xor_sync(0xffffffffu, rs1, 1);
    rs1 += __shfl_xor_sync(0xffffffffu, rs1, 2);
    if (t4 == 0) {
        smf[U_LSUM + qb + g] = rs0;
        smf[U_LSUM + qb + g + 8] = rs1;
    }
    pfK(0, 0); pfV(0, 0); pfM(0, 0); CP_COMMIT();
    __syncthreads();
    if (t < MQ) smf[U_INV + t] = 1.f / smf[U_LSUM + t];
    __syncthreads();

    const float inv0 = smf[U_INV + qb + g];
    const float inv1 = smf[U_INV + qb + g + 8];

    float* wr0 = W + ((size_t)bh * SQ + qt * MQ + qb + g) * SQ;
    float* wr1 = wr0 + (size_t)8 * SQ;

    float accO[8][4];
    #pragma unroll
    for (int j = 0; j < 8; j++)
        accO[j][0] = accO[j][1] = accO[j][2] = accO[j][3] = 0.f;

    // ================= PASS 2: W write + PV =================
    for (int kt = 0; kt < NTILE; kt++) {
        const int cur = kt & 1;
        if (kt < NTILE - 1) {
            pfK(cur ^ 1, kt + 1); pfV(cur ^ 1, kt + 1); pfM(cur ^ 1, kt + 1);
            CP_COMMIT(); CP_WAIT1();
        } else {
            CP_WAIT0();
        }
        __syncthreads();

        const uint32_t* KHb = smu + U_KH + cur * 4096;
        const uint32_t* KLb = smu + U_KL + cur * 4096;
        const uint32_t* VHb = smu + U_VH + cur * 4096;
        const uint32_t* VLb = smu + U_VL + cur * 4096;
        const int* mk = (const int*)(smu + U_MSK + cur * 128);
        const size_t ktb = (size_t)kt * TKEY;

        float c[2][2][2][4];
        qk3(KHb, KLb, 0, c[0]);
        #pragma unroll
        for (int kc2 = 0; kc2 < 8; kc2++) {
            if (kc2 < 7) qk3(KHb, KLb, kc2 + 1, c[(kc2 + 1) & 1]);
            float (&cP)[2][2][4] = c[kc2 & 1];

            int key0 = kc2 * 16 + dlo;
            int m0 = mk[key0], m1 = mk[key0 + 1], m2 = mk[key0 + 8], m3 = mk[key0 + 9];

            float e00 = m0 ? __expf((cP[0][0][0] + cP[0][1][0]) * 0.125f) * inv0 : 0.f;
            float e01 = m1 ? __expf((cP[0][0][1] + cP[0][1][1]) * 0.125f) * inv0 : 0.f;
            float e02 = m0 ? __expf((cP[0][0][2] + cP[0][1][2]) * 0.125f) * inv1 : 0.f;
            float e03 = m1 ? __expf((cP[0][0][3] + cP[0][1][3]) * 0.125f) * inv1 : 0.f;
            float e10 = m2 ? __expf((cP[1][0][0] + cP[1][1][0]) * 0.125f) * inv0 : 0.f;
            float e11 = m3 ? __expf((cP[1][0][1] + cP[1][1][1]) * 0.125f) * inv0 : 0.f;
            float e12 = m2 ? __expf((cP[1][0][2] + cP[1][1][2]) * 0.125f) * inv1 : 0.f;
            float e13 = m3 ? __expf((cP[1][0][3] + cP[1][1][3]) * 0.125f) * inv1 : 0.f;

            size_t cb = ktb + key0;
            *(float2*)(wr0 + cb)     = make_float2(e00, e01);
            *(float2*)(wr1 + cb)     = make_float2(e02, e03);
            *(float2*)(wr0 + cb + 8) = make_float2(e10, e11);
            *(float2*)(wr1 + cb + 8) = make_float2(e12, e13);

            uint32_t aWH[4], aWL[4];
            split2(e00, e01, aWH[0], aWL[0]);
            split2(e02, e03, aWH[1], aWL[1]);
            split2(e10, e11, aWH[2], aWL[2]);
            split2(e12, e13, aWH[3], aWL[3]);

            uint32_t bhh[8][2], bll[8][2];
            #pragma unroll
            for (int ntd = 0; ntd < 8; ntd++) {
                int base = kc2 * 512 + ntd * 64 + lane * 2;
                *(uint2*)bhh[ntd] = *(const uint2*)&VHb[base];
                *(uint2*)bll[ntd] = *(const uint2*)&VLb[base];
            }
            #pragma unroll
            for (int ntd = 0; ntd < 8; ntd++) mma_bf16(accO[ntd], aWH, bhh[ntd]);
            #pragma unroll
            for (int ntd = 0; ntd < 8; ntd++) mma_bf16(accO[ntd], aWL, bhh[ntd]);
            #pragma unroll
            for (int ntd = 0; ntd < 8; ntd++) mma_bf16(accO[ntd], aWH, bll[ntd]);
        }
        __syncthreads();
    }

    // ---- output ----
    float* or0 = Out + ((size_t)bh * SQ + qt * MQ + qb + g) * DDIM + dlo;
    float* or1 = or0 + (size_t)8 * DDIM;
    #pragma unroll
    for (int ntd = 0; ntd < 8; ntd++) {
        *(float2*)(or0 + ntd * 8) = make_float2(accO[ntd][0], accO[ntd][1]);
        *(float2*)(or1 + ntd * 8) = make_float2(accO[ntd][2], accO[ntd][3]);
    }
}

extern "C" void kernel_launch(void* const* d_in, const int* in_sizes, int n_in,
                              void* d_out, int out_size) {
    const float* q = (const float*)d_in[0];
    const float* k = (const float*)d_in[1];
    const float* v = (const float*)d_in[2];
    const int*   m = (const int*)d_in[3];

    float* out = (float*)d_out;
    float* wts = out + (size_t)BB * HH * SQ * DDIM;

    dim3 pgrid(BB * HH * NTILE, 2);
    prep_split<<<pgrid, 1024>>>(k, v);

    cudaFuncSetAttribute(attn7, cudaFuncAttributeMaxDynamicSharedMemorySize, SMEM_BYTES);
    dim3 grid(SQ / MQ, BB * HH);
    attn7<<<grid, NTH, SMEM_BYTES>>>(q, m, out, wts);
}

// round 8
// speedup vs baseline: 1.6010x; 1.1400x over previous
#include <cuda_runtime.h>
#include <cuda_bf16.h>
#include <cstdint>
#include <math.h>

#define BB 2
#define HH 16
#define SQ 2048
#define DDIM 64
#define MQ 128
#define TKEY 128
#define NTILE (SQ / TKEY)
#define NTH 512

// smem layout (u32 units)
#define U_KH 0
#define U_KL 8192
#define U_VH 16384
#define U_VL 24576
#define U_MSK 32768           // [2][128] int
#define U_LSUM 33024          // [2][128] float
#define U_INV  33280          // [128] float
#define SMEM_BYTES (33408 * 4)
#define U_RED U_KH            // reuse K buffers for final accO merge (8192 floats)

// global scratch: frag-native pre-split K/V (hi/lo bf16x2), 512 tiles x 4096 u32
__device__ uint32_t g_KH[32 * 16 * 4096];
__device__ uint32_t g_KL[32 * 16 * 4096];
__device__ uint32_t g_VH[32 * 16 * 4096];
__device__ uint32_t g_VL[32 * 16 * 4096];

static __device__ __forceinline__ uint32_t smem_u32(const void* p) {
    uint32_t a;
    asm("{ .reg .u64 t; cvta.to.shared.u64 t, %1; cvt.u32.u64 %0, t; }" : "=r"(a) : "l"(p));
    return a;
}
static __device__ __forceinline__ void cp16(uint32_t dst, const void* src) {
    asm volatile("cp.async.cg.shared.global [%0], [%1], 16;" :: "r"(dst), "l"(src));
}
#define CP_COMMIT() asm volatile("cp.async.commit_group;" ::: "memory")
#define CP_WAIT0()  asm volatile("cp.async.wait_group 0;" ::: "memory")
#define CP_WAIT1()  asm volatile("cp.async.wait_group 1;" ::: "memory")

static __device__ __forceinline__ void mma_bf16(float* c, const uint32_t* a, const uint32_t* b) {
    asm volatile(
        "mma.sync.aligned.m16n8k16.row.col.f32.bf16.bf16.f32 "
        "{%0,%1,%2,%3}, {%4,%5,%6,%7}, {%8,%9}, {%0,%1,%2,%3};"
        : "+f"(c[0]), "+f"(c[1]), "+f"(c[2]), "+f"(c[3])
        : "r"(a[0]), "r"(a[1]), "r"(a[2]), "r"(a[3]), "r"(b[0]), "r"(b[1]));
}

static __device__ __forceinline__ void split2(float a, float b, uint32_t& hi, uint32_t& lo) {
    __nv_bfloat162 h = __floats2bfloat162_rn(a, b);
    float ra = a - __bfloat162float(__low2bfloat16(h));
    float rb = b - __bfloat162float(__high2bfloat16(h));
    __nv_bfloat162 l = __floats2bfloat162_rn(ra, rb);
    hi = *reinterpret_cast<uint32_t*>(&h);
    lo = *reinterpret_cast<uint32_t*>(&l);
}

// ---------- prep: split K/V once into frag-native global scratch ----------
__global__ __launch_bounds__(1024)
void prep_split(const float* __restrict__ K, const float* __restrict__ V) {
    const int tile = blockIdx.x;
    const int t = threadIdx.x;
    const size_t base = (size_t)tile * TKEY * DDIM;
    if (blockIdx.y == 0) {
        const float2* src = (const float2*)(K + base);
        uint32_t* dH = g_KH + (size_t)tile * 4096;
        uint32_t* dL = g_KL + (size_t)tile * 4096;
        #pragma unroll
        for (int i = 0; i < 4; i++) {
            int idx = i * 1024 + t;
            int key = idx >> 5, dp = idx & 31;
            float2 x = src[idx];
            int slot = (key >> 3) * 256 + (dp >> 3) * 64
                     + ((key & 7) * 4 + (dp & 3)) * 2 + ((dp >> 2) & 1);
            uint32_t hi, lo; split2(x.x, x.y, hi, lo);
            dH[slot] = hi; dL[slot] = lo;
        }
    } else {
        const float* src = V + base;
        uint32_t* dH = g_VH + (size_t)tile * 4096;
        uint32_t* dL = g_VL + (size_t)tile * 4096;
        #pragma unroll
        for (int i = 0; i < 4; i++) {
            int idx = i * 1024 + t;
            int d = idx & 63, kp = idx >> 6;
            float va = src[(size_t)(2 * kp) * DDIM + d];
            float vb = src[(size_t)(2 * kp + 1) * DDIM + d];
            int kc2 = kp >> 3, w8 = kp & 7;
            int slot = kc2 * 512 + (d >> 3) * 64
                     + ((d & 7) * 4 + (w8 & 3)) * 2 + (w8 >> 2);
            uint32_t hi, lo; split2(va, vb, hi, lo);
            dH[slot] = hi; dL[slot] = lo;
        }
    }
}

// ---------- main attention kernel: 16 warps, key-split ----------
__global__ __launch_bounds__(NTH, 1)
void attn8(const float* __restrict__ Q, const int* __restrict__ M,
           float* __restrict__ Out, float* __restrict__ W) {
    extern __shared__ __align__(16) uint32_t smu[];
    float* smf = (float*)smu;
    const uint32_t sb = smem_u32(smu);

    const int t    = threadIdx.x;
    const int lane = t & 31;
    const int wid  = t >> 5;         // 0..15
    const int wq   = wid & 7;        // q-row group
    const int wk   = wid >> 3;       // key half (0/1)
    const int g    = lane >> 2;
    const int t4   = lane & 3;
    const int dlo  = 2 * t4;
    const int qb   = wq * 16;
    const int kc2base = wk * 4;

    const int qt = blockIdx.x;
    const int bh = blockIdx.y;
    const int b  = bh / HH;

    const float* qg = Q + ((size_t)bh * SQ + (size_t)qt * MQ) * DDIM;
    const int*   mg = M + b * SQ;

    auto pfK = [&](int buf, int kt) {
        const uint32_t* sH = g_KH + ((size_t)bh * 16 + kt) * 4096;
        const uint32_t* sL = g_KL + ((size_t)bh * 16 + kt) * 4096;
        const uint32_t dH = sb + (U_KH + buf * 4096) * 4;
        const uint32_t dL = sb + (U_KL + buf * 4096) * 4;
        #pragma unroll
        for (int c = 0; c < 2; c++) {
            int o = (c * NTH + t) * 4;
            cp16(dH + o * 4, sH + o);
            cp16(dL + o * 4, sL + o);
        }
    };
    auto pfV = [&](int buf, int kt) {
        const uint32_t* sH = g_VH + ((size_t)bh * 16 + kt) * 4096;
        const uint32_t* sL = g_VL + ((size_t)bh * 16 + kt) * 4096;
        const uint32_t dH = sb + (U_VH + buf * 4096) * 4;
        const uint32_t dL = sb + (U_VL + buf * 4096) * 4;
        #pragma unroll
        for (int c = 0; c < 2; c++) {
            int o = (c * NTH + t) * 4;
            cp16(dH + o * 4, sH + o);
            cp16(dL + o * 4, sL + o);
        }
    };
    auto pfM = [&](int buf, int kt) {
        if (t < 32) cp16(sb + (U_MSK + buf * 128 + t * 4) * 4, mg + kt * TKEY + t * 4);
    };

    // ---- persistent Q A-fragments (hi/lo) ----
    uint32_t AH[4][4], AL[4][4];
    #pragma unroll
    for (int kc = 0; kc < 4; kc++) {
        const float* r0 = qg + (size_t)(qb + g) * DDIM + kc * 16 + dlo;
        const float* r1 = r0 + 8 * DDIM;
        float2 p0 = *(const float2*)(r0);
        float2 p1 = *(const float2*)(r1);
        float2 p2 = *(const float2*)(r0 + 8);
        float2 p3 = *(const float2*)(r1 + 8);
        split2(p0.x, p0.y, AH[kc][0], AL[kc][0]);
        split2(p1.x, p1.y, AH[kc][1], AL[kc][1]);
        split2(p2.x, p2.y, AH[kc][2], AL[kc][2]);
        split2(p3.x, p3.y, AH[kc][3], AL[kc][3]);
    }

    auto qk2 = [&](const uint32_t* KHb, const uint32_t* KLb, int kc2, float (&c)[2][2][4]) {
        #pragma unroll
        for (int nt = 0; nt < 2; nt++)
            #pragma unroll
            for (int s = 0; s < 2; s++)
                c[nt][s][0] = c[nt][s][1] = c[nt][s][2] = c[nt][s][3] = 0.f;
        #pragma unroll
        for (int kcd = 0; kcd < 4; kcd++) {
            #pragma unroll
            for (int nt = 0; nt < 2; nt++) {
                int base = (kc2 * 2 + nt) * 256 + kcd * 64 + lane * 2;
                uint32_t bh2[2], bl2[2];
                *(uint2*)bh2 = *(const uint2*)&KHb[base];
                *(uint2*)bl2 = *(const uint2*)&KLb[base];
                mma_bf16(c[nt][0], AH[kcd], bh2);
                mma_bf16(c[nt][1], AH[kcd], bl2);
            }
        }
    };
    auto qk3 = [&](const uint32_t* KHb, const uint32_t* KLb, int kc2, float (&c)[2][2][4]) {
        #pragma unroll
        for (int nt = 0; nt < 2; nt++)
            #pragma unroll
            for (int s = 0; s < 2; s++)
                c[nt][s][0] = c[nt][s][1] = c[nt][s][2] = c[nt][s][3] = 0.f;
        #pragma unroll
        for (int kcd = 0; kcd < 4; kcd++) {
            #pragma unroll
            for (int nt = 0; nt < 2; nt++) {
                int base = (kc2 * 2 + nt) * 256 + kcd * 64 + lane * 2;
                uint32_t bh2[2], bl2[2];
                *(uint2*)bh2 = *(const uint2*)&KHb[base];
                *(uint2*)bl2 = *(const uint2*)&KLb[base];
                mma_bf16(c[nt][0], AH[kcd], bh2);
                mma_bf16(c[nt][1], AH[kcd], bl2);
                mma_bf16(c[nt][1], AL[kcd], bh2);
            }
        }
    };

    // ================= PASS 1: row sums (2-term QK, key-split) =================
    pfK(0, 0); pfM(0, 0); CP_COMMIT();

    float rs0 = 0.f, rs1 = 0.f;
    for (int kt = 0; kt < NTILE; kt++) {
        const int cur = kt & 1;
        if (kt < NTILE - 1) {
            pfK(cur ^ 1, kt + 1); pfM(cur ^ 1, kt + 1);
            CP_COMMIT(); CP_WAIT1();
        } else {
            CP_WAIT0();
        }
        __syncthreads();

        const uint32_t* KHb = smu + U_KH + cur * 4096;
        const uint32_t* KLb = smu + U_KL + cur * 4096;
        const int* mk = (const int*)(smu + U_MSK + cur * 128);

        #pragma unroll
        for (int kc2l = 0; kc2l < 4; kc2l++) {
            const int kc2 = kc2base + kc2l;
            float c[2][2][4];
            qk2(KHb, KLb, kc2, c);
            int key0 = kc2 * 16 + dlo;
            int m0 = mk[key0], m1 = mk[key0 + 1], m2 = mk[key0 + 8], m3 = mk[key0 + 9];
            rs0 += (m0 ? __expf((c[0][0][0] + c[0][1][0]) * 0.125f) : 0.f)
                 + (m1 ? __expf((c[0][0][1] + c[0][1][1]) * 0.125f) : 0.f)
                 + (m2 ? __expf((c[1][0][0] + c[1][1][0]) * 0.125f) : 0.f)
                 + (m3 ? __expf((c[1][0][1] + c[1][1][1]) * 0.125f) : 0.f);
            rs1 += (m0 ? __expf((c[0][0][2] + c[0][1][2]) * 0.125f) : 0.f)
                 + (m1 ? __expf((c[0][0][3] + c[0][1][3]) * 0.125f) : 0.f)
                 + (m2 ? __expf((c[1][0][2] + c[1][1][2]) * 0.125f) : 0.f)
                 + (m3 ? __expf((c[1][0][3] + c[1][1][3]) * 0.125f) : 0.f);
        }
        __syncthreads();
    }
    rs0 += __shfl_xor_sync(0xffffffffu, rs0, 1);
    rs0 += __shfl_xor_sync(0xffffffffu, rs0, 2);
    rs1 += __shfl_xor_sync(0xffffffffu, rs1, 1);
    rs1 += __shfl_xor_sync(0xffffffffu, rs1, 2);
    if (t4 == 0) {
        smf[U_LSUM + wk * 128 + qb + g] = rs0;
        smf[U_LSUM + wk * 128 + qb + g + 8] = rs1;
    }
    pfK(0, 0); pfV(0, 0); pfM(0, 0); CP_COMMIT();
    __syncthreads();
    if (t < MQ) smf[U_INV + t] = 1.f / (smf[U_LSUM + t] + smf[U_LSUM + 128 + t]);
    __syncthreads();

    const float inv0 = smf[U_INV + qb + g];
    const float inv1 = smf[U_INV + qb + g + 8];

    float* wr0 = W + ((size_t)bh * SQ + qt * MQ + qb + g) * SQ;
    float* wr1 = wr0 + (size_t)8 * SQ;

    float accO[8][4];
    #pragma unroll
    for (int j = 0; j < 8; j++)
        accO[j][0] = accO[j][1] = accO[j][2] = accO[j][3] = 0.f;

    // ================= PASS 2: W write + PV (key-split) =================
    for (int kt = 0; kt < NTILE; kt++) {
        const int cur = kt & 1;
        if (kt < NTILE - 1) {
            pfK(cur ^ 1, kt + 1); pfV(cur ^ 1, kt + 1); pfM(cur ^ 1, kt + 1);
            CP_COMMIT(); CP_WAIT1();
        } else {
            CP_WAIT0();
        }
        __syncthreads();

        const uint32_t* KHb = smu + U_KH + cur * 4096;
        const uint32_t* KLb = smu + U_KL + cur * 4096;
        const uint32_t* VHb = smu + U_VH + cur * 4096;
        const uint32_t* VLb = smu + U_VL + cur * 4096;
        const int* mk = (const int*)(smu + U_MSK + cur * 128);
        const size_t ktb = (size_t)kt * TKEY;

        #pragma unroll
        for (int kc2l = 0; kc2l < 4; kc2l++) {
            const int kc2 = kc2base + kc2l;
            float c[2][2][4];
            qk3(KHb, KLb, kc2, c);

            int key0 = kc2 * 16 + dlo;
            int m0 = mk[key0], m1 = mk[key0 + 1], m2 = mk[key0 + 8], m3 = mk[key0 + 9];

            float e00 = m0 ? __expf((c[0][0][0] + c[0][1][0]) * 0.125f) * inv0 : 0.f;
            float e01 = m1 ? __expf((c[0][0][1] + c[0][1][1]) * 0.125f) * inv0 : 0.f;
            float e02 = m0 ? __expf((c[0][0][2] + c[0][1][2]) * 0.125f) * inv1 : 0.f;
            float e03 = m1 ? __expf((c[0][0][3] + c[0][1][3]) * 0.125f) * inv1 : 0.f;
            float e10 = m2 ? __expf((c[1][0][0] + c[1][1][0]) * 0.125f) * inv0 : 0.f;
            float e11 = m3 ? __expf((c[1][0][1] + c[1][1][1]) * 0.125f) * inv0 : 0.f;
            float e12 = m2 ? __expf((c[1][0][2] + c[1][1][2]) * 0.125f) * inv1 : 0.f;
            float e13 = m3 ? __expf((c[1][0][3] + c[1][1][3]) * 0.125f) * inv1 : 0.f;

            size_t cb = ktb + key0;
            *(float2*)(wr0 + cb)     = make_float2(e00, e01);
            *(float2*)(wr1 + cb)     = make_float2(e02, e03);
            *(float2*)(wr0 + cb + 8) = make_float2(e10, e11);
            *(float2*)(wr1 + cb + 8) = make_float2(e12, e13);

            uint32_t aWH[4], aWL[4];
            split2(e00, e01, aWH[0], aWL[0]);
            split2(e02, e03, aWH[1], aWL[1]);
            split2(e10, e11, aWH[2], aWL[2]);
            split2(e12, e13, aWH[3], aWL[3]);

            #pragma unroll
            for (int ntd = 0; ntd < 8; ntd++) {
                int base = kc2 * 512 + ntd * 64 + lane * 2;
                uint32_t bh2[2], bl2[2];
                *(uint2*)bh2 = *(const uint2*)&VHb[base];
                *(uint2*)bl2 = *(const uint2*)&VLb[base];
                mma_bf16(accO[ntd], aWH, bh2);
                mma_bf16(accO[ntd], aWL, bh2);
                mma_bf16(accO[ntd], aWH, bl2);
            }
        }
        __syncthreads();
    }

    // ---- merge the two key-halves' accO and write Out ----
    float* red = smf + U_RED;
    if (wk == 1) {
        #pragma unroll
        for (int ntd = 0; ntd < 8; ntd++)
            *(float4*)&red[(wq * 32 + lane) * 32 + ntd * 4] =
                make_float4(accO[ntd][0], accO[ntd][1], accO[ntd][2], accO[ntd][3]);
    }
    __syncthreads();
    if (wk == 0) {
        float* or0 = Out + ((size_t)bh * SQ + qt * MQ + qb + g) * DDIM + dlo;
        float* or1 = or0 + (size_t)8 * DDIM;
        #pragma unroll
        for (int ntd = 0; ntd < 8; ntd++) {
            float4 o = *(float4*)&red[(wq * 32 + lane) * 32 + ntd * 4];
            *(float2*)(or0 + ntd * 8) = make_float2(accO[ntd][0] + o.x, accO[ntd][1] + o.y);
            *(float2*)(or1 + ntd * 8) = make_float2(accO[ntd][2] + o.z, accO[ntd][3] + o.w);
        }
    }
}

extern "C" void kernel_launch(void* const* d_in, const int* in_sizes, int n_in,
                              void* d_out, int out_size) {
    const float* q = (const float*)d_in[0];
    const float* k = (const float*)d_in[1];
    const float* v = (const float*)d_in[2];
    const int*   m = (const int*)d_in[3];

    float* out = (float*)d_out;
    float* wts = out + (size_t)BB * HH * SQ * DDIM;

    dim3 pgrid(BB * HH * NTILE, 2);
    prep_split<<<pgrid, 1024>>>(k, v);

    cudaFuncSetAttribute(attn8, cudaFuncAttributeMaxDynamicSharedMemorySize, SMEM_BYTES);
    dim3 grid(SQ / MQ, BB * HH);
    attn8<<<grid, NTH, SMEM_BYTES>>>(q, m, out, wts);
}

// round 9
// speedup vs baseline: 1.7791x; 1.1112x over previous
#include <cuda_runtime.h>
#include <cuda_bf16.h>
#include <cstdint>
#include <math.h>

#define BB 2
#define HH 16
#define SQ 2048
#define DDIM 64
#define MQ 128
#define TKEY 128
#define NTILE (SQ / TKEY)
#define NTH 512

// smem layout (u32 units)
#define U_KH 0
#define U_KL 8192
#define U_VH 16384
#define U_VL 24576
#define U_MSK 32768           // [2][128] int
#define U_LSUM 33024          // [2][128] float
#define U_INV  33280          // [128] float
#define SMEM_BYTES (33408 * 4)
#define U_RED U_KH            // reuse K buffers for final accO merge

// global scratch: frag-native pre-split K/V (hi/lo bf16x2), 512 tiles x 4096 u32
__device__ uint32_t g_KH[32 * 16 * 4096];
__device__ uint32_t g_KL[32 * 16 * 4096];
__device__ uint32_t g_VH[32 * 16 * 4096];
__device__ uint32_t g_VL[32 * 16 * 4096];

static __device__ __forceinline__ uint32_t smem_u32(const void* p) {
    uint32_t a;
    asm("{ .reg .u64 t; cvta.to.shared.u64 t, %1; cvt.u32.u64 %0, t; }" : "=r"(a) : "l"(p));
    return a;
}
static __device__ __forceinline__ void cp16(uint32_t dst, const void* src) {
    asm volatile("cp.async.cg.shared.global [%0], [%1], 16;" :: "r"(dst), "l"(src));
}
#define CP_COMMIT() asm volatile("cp.async.commit_group;" ::: "memory")
#define CP_WAIT0()  asm volatile("cp.async.wait_group 0;" ::: "memory")

static __device__ __forceinline__ void mma_bf16(float* c, const uint32_t* a, const uint32_t* b) {
    asm volatile(
        "mma.sync.aligned.m16n8k16.row.col.f32.bf16.bf16.f32 "
        "{%0,%1,%2,%3}, {%4,%5,%6,%7}, {%8,%9}, {%0,%1,%2,%3};"
        : "+f"(c[0]), "+f"(c[1]), "+f"(c[2]), "+f"(c[3])
        : "r"(a[0]), "r"(a[1]), "r"(a[2]), "r"(a[3]), "r"(b[0]), "r"(b[1]));
}

static __device__ __forceinline__ void split2(float a, float b, uint32_t& hi, uint32_t& lo) {
    __nv_bfloat162 h = __floats2bfloat162_rn(a, b);
    float ra = a - __bfloat162float(__low2bfloat16(h));
    float rb = b - __bfloat162float(__high2bfloat16(h));
    __nv_bfloat162 l = __floats2bfloat162_rn(ra, rb);
    hi = *reinterpret_cast<uint32_t*>(&h);
    lo = *reinterpret_cast<uint32_t*>(&l);
}

// ---------- prep: split K/V once into frag-native global scratch ----------
__global__ __launch_bounds__(1024)
void prep_split(const float* __restrict__ K, const float* __restrict__ V) {
    const int tile = blockIdx.x;
    const int t = threadIdx.x;
    const size_t base = (size_t)tile * TKEY * DDIM;
    if (blockIdx.y == 0) {
        const float2* src = (const float2*)(K + base);
        uint32_t* dH = g_KH + (size_t)tile * 4096;
        uint32_t* dL = g_KL + (size_t)tile * 4096;
        #pragma unroll
        for (int i = 0; i < 4; i++) {
            int idx = i * 1024 + t;
            int key = idx >> 5, dp = idx & 31;
            float2 x = src[idx];
            int slot = (key >> 3) * 256 + (dp >> 3) * 64
                     + ((key & 7) * 4 + (dp & 3)) * 2 + ((dp >> 2) & 1);
            uint32_t hi, lo; split2(x.x, x.y, hi, lo);
            dH[slot] = hi; dL[slot] = lo;
        }
    } else {
        const float* src = V + base;
        uint32_t* dH = g_VH + (size_t)tile * 4096;
        uint32_t* dL = g_VL + (size_t)tile * 4096;
        #pragma unroll
        for (int i = 0; i < 4; i++) {
            int idx = i * 1024 + t;
            int d = idx & 63, kp = idx >> 6;
            float va = src[(size_t)(2 * kp) * DDIM + d];
            float vb = src[(size_t)(2 * kp + 1) * DDIM + d];
            int kc2 = kp >> 3, w8 = kp & 7;
            int slot = kc2 * 512 + (d >> 3) * 64
                     + ((d & 7) * 4 + (w8 & 3)) * 2 + (w8 >> 2);
            uint32_t hi, lo; split2(va, vb, hi, lo);
            dH[slot] = hi; dL[slot] = lo;
        }
    }
}

// ---------- main attention kernel: 16 warps, key-split ----------
__global__ __launch_bounds__(NTH, 1)
void attn9(const float* __restrict__ Q, const int* __restrict__ M,
           float* __restrict__ Out, float* __restrict__ W) {
    extern __shared__ __align__(16) uint32_t smu[];
    float* smf = (float*)smu;
    const uint32_t sb = smem_u32(smu);

    const int t    = threadIdx.x;
    const int lane = t & 31;
    const int wid  = t >> 5;
    const int wq   = wid & 7;
    const int wk   = wid >> 3;
    const int g    = lane >> 2;
    const int t4   = lane & 3;
    const int dlo  = 2 * t4;
    const int qb   = wq * 16;
    const int kc2base = wk * 4;

    const int qt = blockIdx.x;
    const int bh = blockIdx.y;
    const int b  = bh / HH;

    const float* qg = Q + ((size_t)bh * SQ + (size_t)qt * MQ) * DDIM;
    const int*   mg = M + b * SQ;

    auto pfK = [&](int buf, int kt) {
        const uint32_t* sH = g_KH + ((size_t)bh * 16 + kt) * 4096;
        const uint32_t* sL = g_KL + ((size_t)bh * 16 + kt) * 4096;
        const uint32_t dH = sb + (U_KH + buf * 4096) * 4;
        const uint32_t dL = sb + (U_KL + buf * 4096) * 4;
        #pragma unroll
        for (int c = 0; c < 2; c++) {
            int o = (c * NTH + t) * 4;
            cp16(dH + o * 4, sH + o);
            cp16(dL + o * 4, sL + o);
        }
    };
    auto pfV = [&](int buf, int kt) {
        const uint32_t* sH = g_VH + ((size_t)bh * 16 + kt) * 4096;
        const uint32_t* sL = g_VL + ((size_t)bh * 16 + kt) * 4096;
        const uint32_t dH = sb + (U_VH + buf * 4096) * 4;
        const uint32_t dL = sb + (U_VL + buf * 4096) * 4;
        #pragma unroll
        for (int c = 0; c < 2; c++) {
            int o = (c * NTH + t) * 4;
            cp16(dH + o * 4, sH + o);
            cp16(dL + o * 4, sL + o);
        }
    };
    auto pfM = [&](int buf, int kt) {
        if (t < 32) cp16(sb + (U_MSK + buf * 128 + t * 4) * 4, mg + kt * TKEY + t * 4);
    };

    // ---- persistent Q A-fragments (hi/lo) ----
    uint32_t AH[4][4], AL[4][4];
    #pragma unroll
    for (int kc = 0; kc < 4; kc++) {
        const float* r0 = qg + (size_t)(qb + g) * DDIM + kc * 16 + dlo;
        const float* r1 = r0 + 8 * DDIM;
        float2 p0 = *(const float2*)(r0);
        float2 p1 = *(const float2*)(r1);
        float2 p2 = *(const float2*)(r0 + 8);
        float2 p3 = *(const float2*)(r1 + 8);
        split2(p0.x, p0.y, AH[kc][0], AL[kc][0]);
        split2(p1.x, p1.y, AH[kc][1], AL[kc][1]);
        split2(p2.x, p2.y, AH[kc][2], AL[kc][2]);
        split2(p3.x, p3.y, AH[kc][3], AL[kc][3]);
    }

    // 1-term QK (pass 1): c[nt][4]
    auto qk1 = [&](const uint32_t* KHb, int kc2, float (&c)[2][4]) {
        #pragma unroll
        for (int nt = 0; nt < 2; nt++)
            c[nt][0] = c[nt][1] = c[nt][2] = c[nt][3] = 0.f;
        #pragma unroll
        for (int kcd = 0; kcd < 4; kcd++) {
            #pragma unroll
            for (int nt = 0; nt < 2; nt++) {
                int base = (kc2 * 2 + nt) * 256 + kcd * 64 + lane * 2;
                uint32_t bh2[2];
                *(uint2*)bh2 = *(const uint2*)&KHb[base];
                mma_bf16(c[nt], AH[kcd], bh2);
            }
        }
    };
    // 3-term QK (pass 2): c[nt][chain][4]
    auto qk3 = [&](const uint32_t* KHb, const uint32_t* KLb, int kc2, float (&c)[2][2][4]) {
        #pragma unroll
        for (int nt = 0; nt < 2; nt++)
            #pragma unroll
            for (int s = 0; s < 2; s++)
                c[nt][s][0] = c[nt][s][1] = c[nt][s][2] = c[nt][s][3] = 0.f;
        #pragma unroll
        for (int kcd = 0; kcd < 4; kcd++) {
            #pragma unroll
            for (int nt = 0; nt < 2; nt++) {
                int base = (kc2 * 2 + nt) * 256 + kcd * 64 + lane * 2;
                uint32_t bh2[2], bl2[2];
                *(uint2*)bh2 = *(const uint2*)&KHb[base];
                *(uint2*)bl2 = *(const uint2*)&KLb[base];
                mma_bf16(c[nt][0], AH[kcd], bh2);
                mma_bf16(c[nt][1], AH[kcd], bl2);
                mma_bf16(c[nt][1], AL[kcd], bh2);
            }
        }
    };

    // ================= PASS 1: row sums (1-term QK) =================
    pfK(0, 0); pfM(0, 0); CP_COMMIT();

    float rs0 = 0.f, rs1 = 0.f;
    for (int kt = 0; kt < NTILE; kt++) {
        const int cur = kt & 1;
        CP_WAIT0();
        __syncthreads();                       // publishes cur data; retires reads of nxt buf
        if (kt < NTILE - 1) {
            pfK(cur ^ 1, kt + 1); pfM(cur ^ 1, kt + 1);
            CP_COMMIT();
        }

        const uint32_t* KHb = smu + U_KH + cur * 4096;
        const int* mk = (const int*)(smu + U_MSK + cur * 128);

        #pragma unroll
        for (int kc2l = 0; kc2l < 4; kc2l++) {
            const int kc2 = kc2base + kc2l;
            float c[2][4];
            qk1(KHb, kc2, c);
            int key0 = kc2 * 16 + dlo;
            int m0 = mk[key0], m1 = mk[key0 + 1], m2 = mk[key0 + 8], m3 = mk[key0 + 9];
            rs0 += (m0 ? __expf(c[0][0] * 0.125f) : 0.f)
                 + (m1 ? __expf(c[0][1] * 0.125f) : 0.f)
                 + (m2 ? __expf(c[1][0] * 0.125f) : 0.f)
                 + (m3 ? __expf(c[1][1] * 0.125f) : 0.f);
            rs1 += (m0 ? __expf(c[0][2] * 0.125f) : 0.f)
                 + (m1 ? __expf(c[0][3] * 0.125f) : 0.f)
                 + (m2 ? __expf(c[1][2] * 0.125f) : 0.f)
                 + (m3 ? __expf(c[1][3] * 0.125f) : 0.f);
        }
    }
    rs0 += __shfl_xor_sync(0xffffffffu, rs0, 1);
    rs0 += __shfl_xor_sync(0xffffffffu, rs0, 2);
    rs1 += __shfl_xor_sync(0xffffffffu, rs1, 1);
    rs1 += __shfl_xor_sync(0xffffffffu, rs1, 2);
    if (t4 == 0) {
        smf[U_LSUM + wk * 128 + qb + g] = rs0;
        smf[U_LSUM + wk * 128 + qb + g + 8] = rs1;
    }
    // prefetch pass-2 tile 0 (buf0 last read at kt=14; all warps past kt=15's sync)
    pfK(0, 0); pfV(0, 0); pfM(0, 0); CP_COMMIT();
    __syncthreads();                            // LSUM visible
    if (t < MQ) smf[U_INV + t] = 1.f / (smf[U_LSUM + t] + smf[U_LSUM + 128 + t]);

    float accO[8][4];
    #pragma unroll
    for (int j = 0; j < 8; j++)
        accO[j][0] = accO[j][1] = accO[j][2] = accO[j][3] = 0.f;

    // ================= PASS 2: W write + PV =================
    float inv0 = 0.f, inv1 = 0.f;
    float* wr0 = W + ((size_t)bh * SQ + qt * MQ + qb + g) * SQ;
    float* wr1 = wr0 + (size_t)8 * SQ;

    for (int kt = 0; kt < NTILE; kt++) {
        const int cur = kt & 1;
        CP_WAIT0();
        __syncthreads();                       // publishes cur data + (kt==0) INV
        if (kt == 0) {
            inv0 = smf[U_INV + qb + g];
            inv1 = smf[U_INV + qb + g + 8];
        }
        if (kt < NTILE - 1) {
            pfK(cur ^ 1, kt + 1); pfV(cur ^ 1, kt + 1); pfM(cur ^ 1, kt + 1);
            CP_COMMIT();
        }

        const uint32_t* KHb = smu + U_KH + cur * 4096;
        const uint32_t* KLb = smu + U_KL + cur * 4096;
        const uint32_t* VHb = smu + U_VH + cur * 4096;
        const uint32_t* VLb = smu + U_VL + cur * 4096;
        const int* mk = (const int*)(smu + U_MSK + cur * 128);
        const size_t ktb = (size_t)kt * TKEY;

        #pragma unroll
        for (int kc2l = 0; kc2l < 4; kc2l++) {
            const int kc2 = kc2base + kc2l;
            float c[2][2][4];
            qk3(KHb, KLb, kc2, c);

            int key0 = kc2 * 16 + dlo;
            int m0 = mk[key0], m1 = mk[key0 + 1], m2 = mk[key0 + 8], m3 = mk[key0 + 9];

            float e00 = m0 ? __expf((c[0][0][0] + c[0][1][0]) * 0.125f) * inv0 : 0.f;
            float e01 = m1 ? __expf((c[0][0][1] + c[0][1][1]) * 0.125f) * inv0 : 0.f;
            float e02 = m0 ? __expf((c[0][0][2] + c[0][1][2]) * 0.125f) * inv1 : 0.f;
            float e03 = m1 ? __expf((c[0][0][3] + c[0][1][3]) * 0.125f) * inv1 : 0.f;
            float e10 = m2 ? __expf((c[1][0][0] + c[1][1][0]) * 0.125f) * inv0 : 0.f;
            float e11 = m3 ? __expf((c[1][0][1] + c[1][1][1]) * 0.125f) * inv0 : 0.f;
            float e12 = m2 ? __expf((c[1][0][2] + c[1][1][2]) * 0.125f) * inv1 : 0.f;
            float e13 = m3 ? __expf((c[1][0][3] + c[1][1][3]) * 0.125f) * inv1 : 0.f;

            size_t cb = ktb + key0;
            *(float2*)(wr0 + cb)     = make_float2(e00, e01);
            *(float2*)(wr1 + cb)     = make_float2(e02, e03);
            *(float2*)(wr0 + cb + 8) = make_float2(e10, e11);
            *(float2*)(wr1 + cb + 8) = make_float2(e12, e13);

            uint32_t aWH[4], aWL[4];
            split2(e00, e01, aWH[0], aWL[0]);
            split2(e02, e03, aWH[1], aWL[1]);
            split2(e10, e11, aWH[2], aWL[2]);
            split2(e12, e13, aWH[3], aWL[3]);

            #pragma unroll
            for (int ntd = 0; ntd < 8; ntd++) {
                int base = kc2 * 512 + ntd * 64 + lane * 2;
                uint32_t bh2[2], bl2[2];
                *(uint2*)bh2 = *(const uint2*)&VHb[base];
                *(uint2*)bl2 = *(const uint2*)&VLb[base];
                mma_bf16(accO[ntd], aWH, bh2);
                mma_bf16(accO[ntd], aWL, bh2);
                mma_bf16(accO[ntd], aWH, bl2);
            }
        }
    }

    // ---- merge the two key-halves' accO and write Out ----
    __syncthreads();                            // retire all buffer reads before RED reuse
    float* red = smf + U_RED;
    if (wk == 1) {
        #pragma unroll
        for (int ntd = 0; ntd < 8; ntd++)
            *(float4*)&red[(wq * 32 + lane) * 32 + ntd * 4] =
                make_float4(accO[ntd][0], accO[ntd][1], accO[ntd][2], accO[ntd][3]);
    }
    __syncthreads();
    if (wk == 0) {
        float* or0 = Out + ((size_t)bh * SQ + qt * MQ + qb + g) * DDIM + dlo;
        float* or1 = or0 + (size_t)8 * DDIM;
        #pragma unroll
        for (int ntd = 0; ntd < 8; ntd++) {
            float4 o = *(float4*)&red[(wq * 32 + lane) * 32 + ntd * 4];
            *(float2*)(or0 + ntd * 8) = make_float2(accO[ntd][0] + o.x, accO[ntd][1] + o.y);
            *(float2*)(or1 + ntd * 8) = make_float2(accO[ntd][2] + o.z, accO[ntd][3] + o.w);
        }
    }
}

extern "C" void kernel_launch(void* const* d_in, const int* in_sizes, int n_in,
                              void* d_out, int out_size) {
    const float* q = (const float*)d_in[0];
    const float* k = (const float*)d_in[1];
    const float* v = (const float*)d_in[2];
    const int*   m = (const int*)d_in[3];

    float* out = (float*)d_out;
    float* wts = out + (size_t)BB * HH * SQ * DDIM;

    dim3 pgrid(BB * HH * NTILE, 2);
    prep_split<<<pgrid, 1024>>>(k, v);

    cudaFuncSetAttribute(attn9, cudaFuncAttributeMaxDynamicSharedMemorySize, SMEM_BYTES);
    dim3 grid(SQ / MQ, BB * HH);
    attn9<<<grid, NTH, SMEM_BYTES>>>(q, m, out, wts);
}

// round 10
// speedup vs baseline: 1.9142x; 1.0760x over previous
#include <cuda_runtime.h>
#include <cuda_bf16.h>
#include <cstdint>
#include <math.h>

#define BB 2
#define HH 16
#define SQ 2048
#define DDIM 64
#define MQ 128
#define TKEY 64
#define NTILE (SQ / TKEY)      // 32
#define NTH 256

// smem layout (u32 units): K/V hi/lo double-buffered 64-key tiles (2048 u32 each)
#define U_KH 0                 // [2][2048]
#define U_KL 4096
#define U_VH 8192
#define U_VL 12288
#define U_MSK 16384            // [2][64] int
#define U_INV 16512            // [128] float
#define SMEM_BYTES (16640 * 4)

// global scratch: frag-native pre-split K/V (hi/lo bf16x2), 512 big tiles x 4096 u32
__device__ uint32_t g_KH[32 * 16 * 4096];
__device__ uint32_t g_KL[32 * 16 * 4096];
__device__ uint32_t g_VH[32 * 16 * 4096];
__device__ uint32_t g_VL[32 * 16 * 4096];

static __device__ __forceinline__ uint32_t smem_u32(const void* p) {
    uint32_t a;
    asm("{ .reg .u64 t; cvta.to.shared.u64 t, %1; cvt.u32.u64 %0, t; }" : "=r"(a) : "l"(p));
    return a;
}
static __device__ __forceinline__ void cp16(uint32_t dst, const void* src) {
    asm volatile("cp.async.cg.shared.global [%0], [%1], 16;" :: "r"(dst), "l"(src));
}
#define CP_COMMIT() asm volatile("cp.async.commit_group;" ::: "memory")
#define CP_WAIT0()  asm volatile("cp.async.wait_group 0;" ::: "memory")

static __device__ __forceinline__ void mma_bf16(float* c, const uint32_t* a, const uint32_t* b) {
    asm volatile(
        "mma.sync.aligned.m16n8k16.row.col.f32.bf16.bf16.f32 "
        "{%0,%1,%2,%3}, {%4,%5,%6,%7}, {%8,%9}, {%0,%1,%2,%3};"
        : "+f"(c[0]), "+f"(c[1]), "+f"(c[2]), "+f"(c[3])
        : "r"(a[0]), "r"(a[1]), "r"(a[2]), "r"(a[3]), "r"(b[0]), "r"(b[1]));
}

static __device__ __forceinline__ void split2(float a, float b, uint32_t& hi, uint32_t& lo) {
    __nv_bfloat162 h = __floats2bfloat162_rn(a, b);
    float ra = a - __bfloat162float(__low2bfloat16(h));
    float rb = b - __bfloat162float(__high2bfloat16(h));
    __nv_bfloat162 l = __floats2bfloat162_rn(ra, rb);
    hi = *reinterpret_cast<uint32_t*>(&h);
    lo = *reinterpret_cast<uint32_t*>(&l);
}

// ---------- prep: split K/V once into frag-native global scratch ----------
__global__ __launch_bounds__(1024)
void prep_split(const float* __restrict__ K, const float* __restrict__ V) {
    const int tile = blockIdx.x;               // bh*16 + 128-key tile
    const int t = threadIdx.x;
    const size_t base = (size_t)tile * 128 * DDIM;
    if (blockIdx.y == 0) {
        const float2* src = (const float2*)(K + base);
        uint32_t* dH = g_KH + (size_t)tile * 4096;
        uint32_t* dL = g_KL + (size_t)tile * 4096;
        #pragma unroll
        for (int i = 0; i < 4; i++) {
            int idx = i * 1024 + t;
            int key = idx >> 5, dp = idx & 31;
            float2 x = src[idx];
            int slot = (key >> 3) * 256 + (dp >> 3) * 64
                     + ((key & 7) * 4 + (dp & 3)) * 2 + ((dp >> 2) & 1);
            uint32_t hi, lo; split2(x.x, x.y, hi, lo);
            dH[slot] = hi; dL[slot] = lo;
        }
    } else {
        const float* src = V + base;
        uint32_t* dH = g_VH + (size_t)tile * 4096;
        uint32_t* dL = g_VL + (size_t)tile * 4096;
        #pragma unroll
        for (int i = 0; i < 4; i++) {
            int idx = i * 1024 + t;
            int d = idx & 63, kp = idx >> 6;
            float va = src[(size_t)(2 * kp) * DDIM + d];
            float vb = src[(size_t)(2 * kp + 1) * DDIM + d];
            int kc2 = kp >> 3, w8 = kp & 7;
            int slot = kc2 * 512 + (d >> 3) * 64
                     + ((d & 7) * 4 + (w8 & 3)) * 2 + (w8 >> 2);
            uint32_t hi, lo; split2(va, vb, hi, lo);
            dH[slot] = hi; dL[slot] = lo;
        }
    }
}

// ---------- main attention kernel: 8 warps, 64-key tiles, 2 CTAs/SM ----------
__global__ __launch_bounds__(NTH, 2)
void attn10(const float* __restrict__ Q, const int* __restrict__ M,
            float* __restrict__ Out, float* __restrict__ W) {
    extern __shared__ __align__(16) uint32_t smu[];
    float* smf = (float*)smu;
    const uint32_t sb = smem_u32(smu);

    const int t    = threadIdx.x;
    const int lane = t & 31;
    const int wid  = t >> 5;         // 0..7
    const int g    = lane >> 2;
    const int t4   = lane & 3;
    const int dlo  = 2 * t4;
    const int qb   = wid * 16;

    const int qt = blockIdx.x;
    const int bh = blockIdx.y;
    const int b  = bh / HH;

    const float* qg = Q + ((size_t)bh * SQ + (size_t)qt * MQ) * DDIM;
    const int*   mg = M + b * SQ;

    // 64-key tile kt64: big tile kt64>>1, half kt64&1 (contiguous 2048-u32 range)
    auto pfK = [&](int buf, int kt64) {
        const size_t off = ((size_t)bh * 16 + (kt64 >> 1)) * 4096 + (size_t)(kt64 & 1) * 2048;
        const uint32_t* sH = g_KH + off;
        const uint32_t* sL = g_KL + off;
        const uint32_t dH = sb + (U_KH + buf * 2048) * 4;
        const uint32_t dL = sb + (U_KL + buf * 2048) * 4;
        #pragma unroll
        for (int c = 0; c < 2; c++) {
            int o = (c * NTH + t) * 4;
            cp16(dH + o * 4, sH + o);
            cp16(dL + o * 4, sL + o);
        }
    };
    auto pfV = [&](int buf, int kt64) {
        const size_t off = ((size_t)bh * 16 + (kt64 >> 1)) * 4096 + (size_t)(kt64 & 1) * 2048;
        const uint32_t* sH = g_VH + off;
        const uint32_t* sL = g_VL + off;
        const uint32_t dH = sb + (U_VH + buf * 2048) * 4;
        const uint32_t dL = sb + (U_VL + buf * 2048) * 4;
        #pragma unroll
        for (int c = 0; c < 2; c++) {
            int o = (c * NTH + t) * 4;
            cp16(dH + o * 4, sH + o);
            cp16(dL + o * 4, sL + o);
        }
    };
    auto pfM = [&](int buf, int kt64) {
        if (t < 16) cp16(sb + (U_MSK + buf * 64 + t * 4) * 4, mg + kt64 * TKEY + t * 4);
    };

    // ---- persistent Q A-fragments (hi/lo) ----
    uint32_t AH[4][4], AL[4][4];
    #pragma unroll
    for (int kc = 0; kc < 4; kc++) {
        const float* r0 = qg + (size_t)(qb + g) * DDIM + kc * 16 + dlo;
        const float* r1 = r0 + 8 * DDIM;
        float2 p0 = *(const float2*)(r0);
        float2 p1 = *(const float2*)(r1);
        float2 p2 = *(const float2*)(r0 + 8);
        float2 p3 = *(const float2*)(r1 + 8);
        split2(p0.x, p0.y, AH[kc][0], AL[kc][0]);
        split2(p1.x, p1.y, AH[kc][1], AL[kc][1]);
        split2(p2.x, p2.y, AH[kc][2], AL[kc][2]);
        split2(p3.x, p3.y, AH[kc][3], AL[kc][3]);
    }

    auto qk1 = [&](const uint32_t* KHb, int kc2, float (&c)[2][4]) {
        #pragma unroll
        for (int nt = 0; nt < 2; nt++)
            c[nt][0] = c[nt][1] = c[nt][2] = c[nt][3] = 0.f;
        #pragma unroll
        for (int kcd = 0; kcd < 4; kcd++) {
            #pragma unroll
            for (int nt = 0; nt < 2; nt++) {
                int base = (kc2 * 2 + nt) * 256 + kcd * 64 + lane * 2;
                uint32_t bh2[2];
                *(uint2*)bh2 = *(const uint2*)&KHb[base];
                mma_bf16(c[nt], AH[kcd], bh2);
            }
        }
    };
    auto qk3 = [&](const uint32_t* KHb, const uint32_t* KLb, int kc2, float (&c)[2][2][4]) {
        #pragma unroll
        for (int nt = 0; nt < 2; nt++)
            #pragma unroll
            for (int s = 0; s < 2; s++)
                c[nt][s][0] = c[nt][s][1] = c[nt][s][2] = c[nt][s][3] = 0.f;
        #pragma unroll
        for (int kcd = 0; kcd < 4; kcd++) {
            #pragma unroll
            for (int nt = 0; nt < 2; nt++) {
                int base = (kc2 * 2 + nt) * 256 + kcd * 64 + lane * 2;
                uint32_t bh2[2], bl2[2];
                *(uint2*)bh2 = *(const uint2*)&KHb[base];
                *(uint2*)bl2 = *(const uint2*)&KLb[base];
                mma_bf16(c[nt][0], AH[kcd], bh2);
                mma_bf16(c[nt][1], AH[kcd], bl2);
                mma_bf16(c[nt][1], AL[kcd], bh2);
            }
        }
    };

    // ================= PASS 1: row sums (1-term QK) =================
    pfK(0, 0); pfM(0, 0); CP_COMMIT();

    float rs0 = 0.f, rs1 = 0.f;
    for (int kt = 0; kt < NTILE; kt++) {
        const int cur = kt & 1;
        CP_WAIT0();
        __syncthreads();
        if (kt < NTILE - 1) {
            pfK(cur ^ 1, kt + 1); pfM(cur ^ 1, kt + 1);
            CP_COMMIT();
        }

        const uint32_t* KHb = smu + U_KH + cur * 2048;
        const int* mk = (const int*)(smu + U_MSK + cur * 64);

        #pragma unroll
        for (int kc2 = 0; kc2 < 4; kc2++) {
            float c[2][4];
            qk1(KHb, kc2, c);
            int key0 = kc2 * 16 + dlo;
            int m0 = mk[key0], m1 = mk[key0 + 1], m2 = mk[key0 + 8], m3 = mk[key0 + 9];
            rs0 += (m0 ? __expf(c[0][0] * 0.125f) : 0.f)
                 + (m1 ? __expf(c[0][1] * 0.125f) : 0.f)
                 + (m2 ? __expf(c[1][0] * 0.125f) : 0.f)
                 + (m3 ? __expf(c[1][1] * 0.125f) : 0.f);
            rs1 += (m0 ? __expf(c[0][2] * 0.125f) : 0.f)
                 + (m1 ? __expf(c[0][3] * 0.125f) : 0.f)
                 + (m2 ? __expf(c[1][2] * 0.125f) : 0.f)
                 + (m3 ? __expf(c[1][3] * 0.125f) : 0.f);
        }
    }
    rs0 += __shfl_xor_sync(0xffffffffu, rs0, 1);
    rs0 += __shfl_xor_sync(0xffffffffu, rs0, 2);
    rs1 += __shfl_xor_sync(0xffffffffu, rs1, 1);
    rs1 += __shfl_xor_sync(0xffffffffu, rs1, 2);
    const float inv0 = 1.f / rs0;               // warp-local: each warp owns its rows fully
    const float inv1 = 1.f / rs1;

    // prefetch pass-2 tile 0
    pfK(0, 0); pfV(0, 0); pfM(0, 0); CP_COMMIT();

    float accO[8][4];
    #pragma unroll
    for (int j = 0; j < 8; j++)
        accO[j][0] = accO[j][1] = accO[j][2] = accO[j][3] = 0.f;

    float* wr0 = W + ((size_t)bh * SQ + qt * MQ + qb + g) * SQ;
    float* wr1 = wr0 + (size_t)8 * SQ;

    // ================= PASS 2: W write + PV =================
    for (int kt = 0; kt < NTILE; kt++) {
        const int cur = kt & 1;
        CP_WAIT0();
        __syncthreads();
        if (kt < NTILE - 1) {
            pfK(cur ^ 1, kt + 1); pfV(cur ^ 1, kt + 1); pfM(cur ^ 1, kt + 1);
            CP_COMMIT();
        }

        const uint32_t* KHb = smu + U_KH + cur * 2048;
        const uint32_t* KLb = smu + U_KL + cur * 2048;
        const uint32_t* VHb = smu + U_VH + cur * 2048;
        const uint32_t* VLb = smu + U_VL + cur * 2048;
        const int* mk = (const int*)(smu + U_MSK + cur * 64);
        const size_t ktb = (size_t)kt * TKEY;

        #pragma unroll
        for (int kc2 = 0; kc2 < 4; kc2++) {
            float c[2][2][4];
            qk3(KHb, KLb, kc2, c);

            int key0 = kc2 * 16 + dlo;
            int m0 = mk[key0], m1 = mk[key0 + 1], m2 = mk[key0 + 8], m3 = mk[key0 + 9];

            float e00 = m0 ? __expf((c[0][0][0] + c[0][1][0]) * 0.125f) * inv0 : 0.f;
            float e01 = m1 ? __expf((c[0][0][1] + c[0][1][1]) * 0.125f) * inv0 : 0.f;
            float e02 = m0 ? __expf((c[0][0][2] + c[0][1][2]) * 0.125f) * inv1 : 0.f;
            float e03 = m1 ? __expf((c[0][0][3] + c[0][1][3]) * 0.125f) * inv1 : 0.f;
            float e10 = m2 ? __expf((c[1][0][0] + c[1][1][0]) * 0.125f) * inv0 : 0.f;
            float e11 = m3 ? __expf((c[1][0][1] + c[1][1][1]) * 0.125f) * inv0 : 0.f;
            float e12 = m2 ? __expf((c[1][0][2] + c[1][1][2]) * 0.125f) * inv1 : 0.f;
            float e13 = m3 ? __expf((c[1][0][3] + c[1][1][3]) * 0.125f) * inv1 : 0.f;

            size_t cb = ktb + key0;
            *(float2*)(wr0 + cb)     = make_float2(e00, e01);
            *(float2*)(wr1 + cb)     = make_float2(e02, e03);
            *(float2*)(wr0 + cb + 8) = make_float2(e10, e11);
            *(float2*)(wr1 + cb + 8) = make_float2(e12, e13);

            uint32_t aWH[4], aWL[4];
            split2(e00, e01, aWH[0], aWL[0]);
            split2(e02, e03, aWH[1], aWL[1]);
            split2(e10, e11, aWH[2], aWL[2]);
            split2(e12, e13, aWH[3], aWL[3]);

            #pragma unroll
            for (int ntd = 0; ntd < 8; ntd++) {
                int base = kc2 * 512 + ntd * 64 + lane * 2;
                uint32_t bh2[2], bl2[2];
                *(uint2*)bh2 = *(const uint2*)&VHb[base];
                *(uint2*)bl2 = *(const uint2*)&VLb[base];
                mma_bf16(accO[ntd], aWH, bh2);
                mma_bf16(accO[ntd], aWL, bh2);
                mma_bf16(accO[ntd], aWH, bl2);
            }
        }
    }

    // ---- output (warp-owned, direct) ----
    float* or0 = Out + ((size_t)bh * SQ + qt * MQ + qb + g) * DDIM + dlo;
    float* or1 = or0 + (size_t)8 * DDIM;
    #pragma unroll
    for (int ntd = 0; ntd < 8; ntd++) {
        *(float2*)(or0 + ntd * 8) = make_float2(accO[ntd][0], accO[ntd][1]);
        *(float2*)(or1 + ntd * 8) = make_float2(accO[ntd][2], accO[ntd][3]);
    }
}

extern "C" void kernel_launch(void* const* d_in, const int* in_sizes, int n_in,
                              void* d_out, int out_size) {
    const float* q = (const float*)d_in[0];
    const float* k = (const float*)d_in[1];
    const float* v = (const float*)d_in[2];
    const int*   m = (const int*)d_in[3];

    float* out = (float*)d_out;
    float* wts = out + (size_t)BB * HH * SQ * DDIM;

    dim3 pgrid(BB * HH * 16, 2);
    prep_split<<<pgrid, 1024>>>(k, v);

    cudaFuncSetAttribute(attn10, cudaFuncAttributeMaxDynamicSharedMemorySize, SMEM_BYTES);
    dim3 grid(SQ / MQ, BB * HH);
    attn10<<<grid, NTH, SMEM_BYTES>>>(q, m, out, wts);
}

// round 11
// speedup vs baseline: 2.0704x; 1.0816x over previous
#include <cuda_runtime.h>
#include <cuda_bf16.h>
#include <cstdint>
#include <math.h>

#define BB 2
#define HH 16
#define SQ 2048
#define DDIM 64
#define MQ 128
#define TKEY 64
#define NTILE (SQ / TKEY)      // 32 (pass 2)
#define NBIG  16               // pass-1 128-key tiles
#define NTH 256
#define C_SCALE 0.18033688011110543f   // 0.125 * log2(e)

// smem layout (u32 units)
#define U_KH 0                 // pass2: [2][2048]; pass1: bufs [2][4096] span U_KH+U_KL
#define U_KL 4096
#define U_VH 8192
#define U_VL 12288
#define U_MSK 16384            // [2][128] int
#define SMEM_BYTES (16640 * 4)

// global scratch: frag-native pre-split K/V (hi/lo bf16x2), 512 big tiles x 4096 u32
__device__ uint32_t g_KH[32 * 16 * 4096];
__device__ uint32_t g_KL[32 * 16 * 4096];
__device__ uint32_t g_VH[32 * 16 * 4096];
__device__ uint32_t g_VL[32 * 16 * 4096];

static __device__ __forceinline__ uint32_t smem_u32(const void* p) {
    uint32_t a;
    asm("{ .reg .u64 t; cvta.to.shared.u64 t, %1; cvt.u32.u64 %0, t; }" : "=r"(a) : "l"(p));
    return a;
}
static __device__ __forceinline__ void cp16(uint32_t dst, const void* src) {
    asm volatile("cp.async.cg.shared.global [%0], [%1], 16;" :: "r"(dst), "l"(src));
}
#define CP_COMMIT() asm volatile("cp.async.commit_group;" ::: "memory")
#define CP_WAIT0()  asm volatile("cp.async.wait_group 0;" ::: "memory")

static __device__ __forceinline__ float ex2f(float x) {
    float y; asm("ex2.approx.f32 %0, %1;" : "=f"(y) : "f"(x)); return y;
}
static __device__ __forceinline__ float lg2f(float x) {
    float y; asm("lg2.approx.f32 %0, %1;" : "=f"(y) : "f"(x)); return y;
}

static __device__ __forceinline__ void mma_bf16(float* c, const uint32_t* a, const uint32_t* b) {
    asm volatile(
        "mma.sync.aligned.m16n8k16.row.col.f32.bf16.bf16.f32 "
        "{%0,%1,%2,%3}, {%4,%5,%6,%7}, {%8,%9}, {%0,%1,%2,%3};"
        : "+f"(c[0]), "+f"(c[1]), "+f"(c[2]), "+f"(c[3])
        : "r"(a[0]), "r"(a[1]), "r"(a[2]), "r"(a[3]), "r"(b[0]), "r"(b[1]));
}

static __device__ __forceinline__ void split2(float a, float b, uint32_t& hi, uint32_t& lo) {
    __nv_bfloat162 h = __floats2bfloat162_rn(a, b);
    float ra = a - __bfloat162float(__low2bfloat16(h));
    float rb = b - __bfloat162float(__high2bfloat16(h));
    __nv_bfloat162 l = __floats2bfloat162_rn(ra, rb);
    hi = *reinterpret_cast<uint32_t*>(&h);
    lo = *reinterpret_cast<uint32_t*>(&l);
}

// ---------- prep: split K/V once into frag-native global scratch ----------
__global__ __launch_bounds__(1024)
void prep_split(const float* __restrict__ K, const float* __restrict__ V) {
    const int tile = blockIdx.x;
    const int t = threadIdx.x;
    const size_t base = (size_t)tile * 128 * DDIM;
    if (blockIdx.y == 0) {
        const float2* src = (const float2*)(K + base);
        uint32_t* dH = g_KH + (size_t)tile * 4096;
        uint32_t* dL = g_KL + (size_t)tile * 4096;
        #pragma unroll
        for (int i = 0; i < 4; i++) {
            int idx = i * 1024 + t;
            int key = idx >> 5, dp = idx & 31;
            float2 x = src[idx];
            int slot = (key >> 3) * 256 + (dp >> 3) * 64
                     + ((key & 7) * 4 + (dp & 3)) * 2 + ((dp >> 2) & 1);
            uint32_t hi, lo; split2(x.x, x.y, hi, lo);
            dH[slot] = hi; dL[slot] = lo;
        }
    } else {
        const float* src = V + base;
        uint32_t* dH = g_VH + (size_t)tile * 4096;
        uint32_t* dL = g_VL + (size_t)tile * 4096;
        #pragma unroll
        for (int i = 0; i < 4; i++) {
            int idx = i * 1024 + t;
            int d = idx & 63, kp = idx >> 6;
            float va = src[(size_t)(2 * kp) * DDIM + d];
            float vb = src[(size_t)(2 * kp + 1) * DDIM + d];
            int kc2 = kp >> 3, w8 = kp & 7;
            int slot = kc2 * 512 + (d >> 3) * 64
                     + ((d & 7) * 4 + (w8 & 3)) * 2 + (w8 >> 2);
            uint32_t hi, lo; split2(va, vb, hi, lo);
            dH[slot] = hi; dL[slot] = lo;
        }
    }
}

// ---------- main attention kernel: 8 warps, 2 CTAs/SM ----------
__global__ __launch_bounds__(NTH, 2)
void attn11(const float* __restrict__ Q, const int* __restrict__ M,
            float* __restrict__ Out, float* __restrict__ W) {
    extern __shared__ __align__(16) uint32_t smu[];
    const uint32_t sb = smem_u32(smu);

    const int t    = threadIdx.x;
    const int lane = t & 31;
    const int wid  = t >> 5;
    const int g    = lane >> 2;
    const int t4   = lane & 3;
    const int dlo  = 2 * t4;
    const int qb   = wid * 16;

    const int qt = blockIdx.x;
    const int bh = blockIdx.y;
    const int b  = bh / HH;

    const float* qg = Q + ((size_t)bh * SQ + (size_t)qt * MQ) * DDIM;
    const int*   mg = M + b * SQ;

    // ---- pass-1 prefetchers: 128-key tiles, K-hi only ----
    auto pfK1 = [&](int buf, int bt) {
        const uint32_t* sH = g_KH + ((size_t)bh * 16 + bt) * 4096;
        const uint32_t d = sb + (uint32_t)buf * 4096 * 4;
        #pragma unroll
        for (int c = 0; c < 4; c++) {
            int o = (c * NTH + t) * 4;
            cp16(d + o * 4, sH + o);
        }
    };
    auto pfM1 = [&](int buf, int bt) {
        if (t < 32) cp16(sb + (U_MSK + buf * 128 + t * 4) * 4, mg + bt * 128 + t * 4);
    };

    // ---- pass-2 prefetchers: 64-key tiles ----
    auto pfK = [&](int buf, int kt64) {
        const size_t off = ((size_t)bh * 16 + (kt64 >> 1)) * 4096 + (size_t)(kt64 & 1) * 2048;
        const uint32_t* sH = g_KH + off;
        const uint32_t* sL = g_KL + off;
        const uint32_t dH = sb + (U_KH + buf * 2048) * 4;
        const uint32_t dL = sb + (U_KL + buf * 2048) * 4;
        #pragma unroll
        for (int c = 0; c < 2; c++) {
            int o = (c * NTH + t) * 4;
            cp16(dH + o * 4, sH + o);
            cp16(dL + o * 4, sL + o);
        }
    };
    auto pfV = [&](int buf, int kt64) {
        const size_t off = ((size_t)bh * 16 + (kt64 >> 1)) * 4096 + (size_t)(kt64 & 1) * 2048;
        const uint32_t* sH = g_VH + off;
        const uint32_t* sL = g_VL + off;
        const uint32_t dH = sb + (U_VH + buf * 2048) * 4;
        const uint32_t dL = sb + (U_VL + buf * 2048) * 4;
        #pragma unroll
        for (int c = 0; c < 2; c++) {
            int o = (c * NTH + t) * 4;
            cp16(dH + o * 4, sH + o);
            cp16(dL + o * 4, sL + o);
        }
    };
    auto pfM = [&](int buf, int kt64) {
        if (t < 16) cp16(sb + (U_MSK + buf * 128 + t * 4) * 4, mg + kt64 * TKEY + t * 4);
    };

    // ---- persistent Q A-fragments (hi/lo) ----
    uint32_t AH[4][4], AL[4][4];
    #pragma unroll
    for (int kc = 0; kc < 4; kc++) {
        const float* r0 = qg + (size_t)(qb + g) * DDIM + kc * 16 + dlo;
        const float* r1 = r0 + 8 * DDIM;
        float2 p0 = *(const float2*)(r0);
        float2 p1 = *(const float2*)(r1);
        float2 p2 = *(const float2*)(r0 + 8);
        float2 p3 = *(const float2*)(r1 + 8);
        split2(p0.x, p0.y, AH[kc][0], AL[kc][0]);
        split2(p1.x, p1.y, AH[kc][1], AL[kc][1]);
        split2(p2.x, p2.y, AH[kc][2], AL[kc][2]);
        split2(p3.x, p3.y, AH[kc][3], AL[kc][3]);
    }

    auto qk1 = [&](const uint32_t* KHb, int kc2, float (&c)[2][4]) {
        #pragma unroll
        for (int nt = 0; nt < 2; nt++)
            c[nt][0] = c[nt][1] = c[nt][2] = c[nt][3] = 0.f;
        #pragma unroll
        for (int kcd = 0; kcd < 4; kcd++) {
            #pragma unroll
            for (int nt = 0; nt < 2; nt++) {
                int base = (kc2 * 2 + nt) * 256 + kcd * 64 + lane * 2;
                uint32_t bh2[2];
                *(uint2*)bh2 = *(const uint2*)&KHb[base];
                mma_bf16(c[nt], AH[kcd], bh2);
            }
        }
    };
    auto qk3 = [&](const uint32_t* KHb, const uint32_t* KLb, int kc2, float (&c)[2][2][4]) {
        #pragma unroll
        for (int nt = 0; nt < 2; nt++)
            #pragma unroll
            for (int s = 0; s < 2; s++)
                c[nt][s][0] = c[nt][s][1] = c[nt][s][2] = c[nt][s][3] = 0.f;
        #pragma unroll
        for (int kcd = 0; kcd < 4; kcd++) {
            #pragma unroll
            for (int nt = 0; nt < 2; nt++) {
                int base = (kc2 * 2 + nt) * 256 + kcd * 64 + lane * 2;
                uint32_t bh2[2], bl2[2];
                *(uint2*)bh2 = *(const uint2*)&KHb[base];
                *(uint2*)bl2 = *(const uint2*)&KLb[base];
                mma_bf16(c[nt][0], AH[kcd], bh2);
                mma_bf16(c[nt][1], AH[kcd], bl2);
                mma_bf16(c[nt][1], AL[kcd], bh2);
            }
        }
    };

    // ================= PASS 1: row sums (1-term QK, 128-key tiles, K-hi only) =================
    pfK1(0, 0); pfM1(0, 0); CP_COMMIT();

    float rs0 = 0.f, rs1 = 0.f;
    for (int bt = 0; bt < NBIG; bt++) {
        const int cur = bt & 1;
        CP_WAIT0();
        __syncthreads();
        if (bt < NBIG - 1) {
            pfK1(cur ^ 1, bt + 1); pfM1(cur ^ 1, bt + 1);
            CP_COMMIT();
        }

        const uint32_t* KHb = smu + cur * 4096;
        const int* mk = (const int*)(smu + U_MSK + cur * 128);

        #pragma unroll
        for (int kc2 = 0; kc2 < 8; kc2++) {
            float c[2][4];
            qk1(KHb, kc2, c);
            int key0 = kc2 * 16 + dlo;
            int m0 = mk[key0], m1 = mk[key0 + 1], m2 = mk[key0 + 8], m3 = mk[key0 + 9];
            rs0 += (m0 ? ex2f(c[0][0] * C_SCALE) : 0.f)
                 + (m1 ? ex2f(c[0][1] * C_SCALE) : 0.f)
                 + (m2 ? ex2f(c[1][0] * C_SCALE) : 0.f)
                 + (m3 ? ex2f(c[1][1] * C_SCALE) : 0.f);
            rs1 += (m0 ? ex2f(c[0][2] * C_SCALE) : 0.f)
                 + (m1 ? ex2f(c[0][3] * C_SCALE) : 0.f)
                 + (m2 ? ex2f(c[1][2] * C_SCALE) : 0.f)
                 + (m3 ? ex2f(c[1][3] * C_SCALE) : 0.f);
        }
    }
    rs0 += __shfl_xor_sync(0xffffffffu, rs0, 1);
    rs0 += __shfl_xor_sync(0xffffffffu, rs0, 2);
    rs1 += __shfl_xor_sync(0xffffffffu, rs1, 1);
    rs1 += __shfl_xor_sync(0xffffffffu, rs1, 2);
    const float li0 = -lg2f(rs0);               // log2(1/rs)
    const float li1 = -lg2f(rs1);

    // pass-1 buffers overlap pass-2's KL region: must retire all pass-1 reads first
    __syncthreads();
    pfK(0, 0); pfV(0, 0); pfM(0, 0); CP_COMMIT();

    float accO[8][4];
    #pragma unroll
    for (int j = 0; j < 8; j++)
        accO[j][0] = accO[j][1] = accO[j][2] = accO[j][3] = 0.f;

    float* wr0 = W + ((size_t)bh * SQ + qt * MQ + qb + g) * SQ;
    float* wr1 = wr0 + (size_t)8 * SQ;

    // ================= PASS 2: W write + PV =================
    for (int kt = 0; kt < NTILE; kt++) {
        const int cur = kt & 1;
        CP_WAIT0();
        __syncthreads();
        if (kt < NTILE - 1) {
            pfK(cur ^ 1, kt + 1); pfV(cur ^ 1, kt + 1); pfM(cur ^ 1, kt + 1);
            CP_COMMIT();
        }

        const uint32_t* KHb = smu + U_KH + cur * 2048;
        const uint32_t* KLb = smu + U_KL + cur * 2048;
        const uint32_t* VHb = smu + U_VH + cur * 2048;
        const uint32_t* VLb = smu + U_VL + cur * 2048;
        const int* mk = (const int*)(smu + U_MSK + cur * 128);
        const size_t ktb = (size_t)kt * TKEY;

        #pragma unroll
        for (int kc2 = 0; kc2 < 4; kc2++) {
            float c[2][2][4];
            qk3(KHb, KLb, kc2, c);

            int key0 = kc2 * 16 + dlo;
            int m0 = mk[key0], m1 = mk[key0 + 1], m2 = mk[key0 + 8], m3 = mk[key0 + 9];

            float e00 = m0 ? ex2f(fmaf(c[0][0][0] + c[0][1][0], C_SCALE, li0)) : 0.f;
            float e01 = m1 ? ex2f(fmaf(c[0][0][1] + c[0][1][1], C_SCALE, li0)) : 0.f;
            float e02 = m0 ? ex2f(fmaf(c[0][0][2] + c[0][1][2], C_SCALE, li1)) : 0.f;
            float e03 = m1 ? ex2f(fmaf(c[0][0][3] + c[0][1][3], C_SCALE, li1)) : 0.f;
            float e10 = m2 ? ex2f(fmaf(c[1][0][0] + c[1][1][0], C_SCALE, li0)) : 0.f;
            float e11 = m3 ? ex2f(fmaf(c[1][0][1] + c[1][1][1], C_SCALE, li0)) : 0.f;
            float e12 = m2 ? ex2f(fmaf(c[1][0][2] + c[1][1][2], C_SCALE, li1)) : 0.f;
            float e13 = m3 ? ex2f(fmaf(c[1][0][3] + c[1][1][3], C_SCALE, li1)) : 0.f;

            size_t cb = ktb + key0;
            *(float2*)(wr0 + cb)     = make_float2(e00, e01);
            *(float2*)(wr1 + cb)     = make_float2(e02, e03);
            *(float2*)(wr0 + cb + 8) = make_float2(e10, e11);
            *(float2*)(wr1 + cb + 8) = make_float2(e12, e13);

            uint32_t aWH[4], aWL[4];
            split2(e00, e01, aWH[0], aWL[0]);
            split2(e02, e03, aWH[1], aWL[1]);
            split2(e10, e11, aWH[2], aWL[2]);
            split2(e12, e13, aWH[3], aWL[3]);

            #pragma unroll
            for (int ntd = 0; ntd < 8; ntd++) {
                int base = kc2 * 512 + ntd * 64 + lane * 2;
                uint32_t bh2[2], bl2[2];
                *(uint2*)bh2 = *(const uint2*)&VHb[base];
                *(uint2*)bl2 = *(const uint2*)&VLb[base];
                mma_bf16(accO[ntd], aWH, bh2);
                mma_bf16(accO[ntd], aWL, bh2);
                mma_bf16(accO[ntd], aWH, bl2);
            }
        }
    }

    // ---- output (warp-owned, direct) ----
    float* or0 = Out + ((size_t)bh * SQ + qt * MQ + qb + g) * DDIM + dlo;
    float* or1 = or0 + (size_t)8 * DDIM;
    #pragma unroll
    for (int ntd = 0; ntd < 8; ntd++) {
        *(float2*)(or0 + ntd * 8) = make_float2(accO[ntd][0], accO[ntd][1]);
        *(float2*)(or1 + ntd * 8) = make_float2(accO[ntd][2], accO[ntd][3]);
    }
}

extern "C" void kernel_launch(void* const* d_in, const int* in_sizes, int n_in,
                              void* d_out, int out_size) {
    const float* q = (const float*)d_in[0];
    const float* k = (const float*)d_in[1];
    const float* v = (const float*)d_in[2];
    const int*   m = (const int*)d_in[3];

    float* out = (float*)d_out;
    float* wts = out + (size_t)BB * HH * SQ * DDIM;

    dim3 pgrid(BB * HH * 16, 2);
    prep_split<<<pgrid, 1024>>>(k, v);

    cudaFuncSetAttribute(attn11, cudaFuncAttributeMaxDynamicSharedMemorySize, SMEM_BYTES);
    dim3 grid(SQ / MQ, BB * HH);
    attn11<<<grid, NTH, SMEM_BYTES>>>(q, m, out, wts);
}